// round 11
// baseline (speedup 1.0000x reference)
#include <cuda_runtime.h>
#include <cuda_bf16.h>
#include <cstdint>
#include <math.h>

#define NN 50000
#define RPAD 50176
#define EE 800000
#define KH 20
#define SBLK 196

// ---------------- scratch ----------------
__device__ float g_XL[(size_t)RPAD * 224];
__device__ float g_A0[(size_t)RPAD * 224];
__device__ float g_A1[(size_t)RPAD * 224];
__device__ float g_AC[(size_t)RPAD * 224];
__device__ __nv_bfloat16 g_Ahi[(size_t)RPAD * 256];
__device__ __nv_bfloat16 g_Alo[(size_t)RPAD * 256];
__device__ __nv_bfloat16 g_Wexp[4644864];
__device__ float  g_deg[NN];
__device__ float  g_dis[NN];
__device__ int    g_cnt[NN];
__device__ int    g_rowptr[NN + 1];
__device__ int    g_cursor[NN];
__device__ int    g_bsum[256];
__device__ int    g_boff[256];
__device__ float2 g_cv[EE];

// ---------------- bf16 mma helper ----------------
__device__ __forceinline__ void mma_bf16(float* c, const uint32_t* a, const uint32_t* b) {
    asm volatile(
        "mma.sync.aligned.m16n8k16.row.col.f32.bf16.bf16.f32 "
        "{%0,%1,%2,%3}, {%4,%5,%6,%7}, {%8,%9}, {%0,%1,%2,%3};"
        : "+f"(c[0]), "+f"(c[1]), "+f"(c[2]), "+f"(c[3])
        : "r"(a[0]), "r"(a[1]), "r"(a[2]), "r"(a[3]), "r"(b[0]), "r"(b[1]));
}

// ---------------- CSR build ----------------
__global__ void k_zero_nodes() {
    int i = blockIdx.x * blockDim.x + threadIdx.x;
    if (i < NN) { g_deg[i] = 0.f; g_cnt[i] = 0; }
}
__global__ void k_degcnt(const int* __restrict__ ei, const float* __restrict__ ew) {
    int e = blockIdx.x * blockDim.x + threadIdx.x;
    if (e < EE) {
        int d = ei[EE + e];
        atomicAdd(&g_deg[d], ew[e]);
        atomicAdd(&g_cnt[d], 1);
    }
}
__global__ void k_dis() {
    int i = blockIdx.x * blockDim.x + threadIdx.x;
    if (i < NN) {
        float d = g_deg[i];
        g_dis[i] = (d > 0.f) ? rsqrtf(d) : 0.f;
    }
}
__global__ void k_bsum() {
    __shared__ int sh[256];
    int t = threadIdx.x, i = blockIdx.x * 256 + t;
    sh[t] = (i < NN) ? g_cnt[i] : 0;
    __syncthreads();
    for (int o = 128; o; o >>= 1) {
        if (t < o) sh[t] += sh[t + o];
        __syncthreads();
    }
    if (!t) g_bsum[blockIdx.x] = sh[0];
}
__global__ void k_bscan() {
    __shared__ int sh[256];
    int t = threadIdx.x;
    int v = (t < SBLK) ? g_bsum[t] : 0;
    sh[t] = v;
    __syncthreads();
    for (int o = 1; o < 256; o <<= 1) {
        int u = (t >= o) ? sh[t - o] : 0;
        __syncthreads();
        sh[t] += u;
        __syncthreads();
    }
    if (t < SBLK) g_boff[t] = sh[t] - v;
}
__global__ void k_wptr() {
    __shared__ int sh[256];
    int t = threadIdx.x, i = blockIdx.x * 256 + t;
    int v = (i < NN) ? g_cnt[i] : 0;
    sh[t] = v;
    __syncthreads();
    for (int o = 1; o < 256; o <<= 1) {
        int u = (t >= o) ? sh[t - o] : 0;
        __syncthreads();
        sh[t] += u;
        __syncthreads();
    }
    int excl = sh[t] - v + g_boff[blockIdx.x];
    if (i < NN) {
        g_rowptr[i] = excl;
        g_cursor[i] = excl;
        if (i == NN - 1) g_rowptr[NN] = excl + v;
    }
}
__global__ void k_scatter(const int* __restrict__ ei, const float* __restrict__ ew) {
    int e = blockIdx.x * blockDim.x + threadIdx.x;
    if (e < EE) {
        int s = ei[e];
        int d = ei[EE + e];
        int p = atomicAdd(&g_cursor[d], 1);
        float2 cv;
        cv.x = __int_as_float(s);
        cv.y = g_dis[s] * ew[e] * g_dis[d];
        g_cv[p] = cv;
    }
}

// ---------------- propagation (optionally emits bf16 hi/lo planes) ------------
template <int CH, bool PL>
__global__ void __launch_bounds__(256) k_prop(const float* __restrict__ hin,
                                              float* __restrict__ hout) {
    int w = (blockIdx.x * 256 + threadIdx.x) >> 5;
    if (w >= NN) return;
    int lane = threadIdx.x & 31;
    int beg = g_rowptr[w], end = g_rowptr[w + 1];
    const int S = CH * 32;
    float acc[CH];
#pragma unroll
    for (int t = 0; t < CH; ++t) acc[t] = 0.f;
    int p = beg;
    for (; p + 2 <= end; p += 2) {
        float2 cv0 = __ldg(&g_cv[p]);
        float2 cv1 = __ldg(&g_cv[p + 1]);
        const float* r0 = hin + (size_t)__float_as_int(cv0.x) * S + lane;
        const float* r1 = hin + (size_t)__float_as_int(cv1.x) * S + lane;
#pragma unroll
        for (int t = 0; t < CH; ++t) acc[t] += cv0.y * __ldg(r0 + 32 * t);
#pragma unroll
        for (int t = 0; t < CH; ++t) acc[t] += cv1.y * __ldg(r1 + 32 * t);
    }
    if (p < end) {
        float2 cv = __ldg(&g_cv[p]);
        const float* r = hin + (size_t)__float_as_int(cv.x) * S + lane;
#pragma unroll
        for (int t = 0; t < CH; ++t) acc[t] += cv.y * __ldg(r + 32 * t);
    }
    float* o = hout + (size_t)w * S + lane;
#pragma unroll
    for (int t = 0; t < CH; ++t) {
        o[32 * t] = acc[t];
        if (PL) {
            __nv_bfloat16 h = __float2bfloat16(acc[t]);
            size_t idx = (size_t)w * S + 32 * t + lane;
            g_Ahi[idx] = h;
            g_Alo[idx] = __float2bfloat16(acc[t] - __bfloat162float(h));
        }
    }
}

// ---------------- expand fp32 activations into hi/lo planes ------------------
__global__ void k_expand(const float* __restrict__ src, int sX, int Kpad) {
    int idx = blockIdx.x * 256 + threadIdx.x;
    if (idx >= NN * Kpad) return;
    int w = idx / Kpad, c = idx - w * Kpad;
    float v = src[(size_t)w * sX + c];   // tail-col over-read: finite garbage, W rows are 0
    __nv_bfloat16 h = __float2bfloat16(v);
    g_Ahi[idx] = h;
    g_Alo[idx] = __float2bfloat16(v - __bfloat162float(h));
}

// ---------------- expand weights: [21,Cin,Cout] -> [21][Npad][3*Kpad] bf16 ----
// Row n holds k-contiguous [W_hi(:,n) | W_hi(:,n) | W_lo(:,n)] pairing A segs
// [hi | lo | hi].
__global__ void k_wexp(const float* __restrict__ W, int Cin, int Cout,
                       int Npad, int Kpad, __nv_bfloat16* __restrict__ dst) {
    int idx = blockIdx.x * 256 + threadIdx.x;
    int per = Npad * 3 * Kpad;
    if (idx >= 21 * per) return;
    int k = idx / per;
    int r = idx - k * per;
    int n = r / (3 * Kpad);
    int j = r - n * 3 * Kpad;
    int seg = j / Kpad, ki = j - seg * Kpad;
    float v = (n < Cout && ki < Cin)
                  ? __ldg(&W[(size_t)k * Cin * Cout + (size_t)ki * Cout + n]) : 0.f;
    __nv_bfloat16 h = __float2bfloat16(v);
    dst[idx] = (seg < 2) ? h : __float2bfloat16(v - __bfloat162float(h));
}

// ---------------- bf16 tensor GEMM: 128x64 tile, m16n8k16, 3-term split ------
// MODE 0: D = P   MODE 1: D += P   MODE 2: D2 = relu(D + P + bias)
#define BM 128
#define BN 64
#define BK 32
#define ASTR 40
template <int MODE>
__global__ void __launch_bounds__(256) k_gemm_bf(int Kpad,
                                                 const __nv_bfloat16* __restrict__ Wx,
                                                 int wRow,
                                                 float* __restrict__ D, int sD, int Cout,
                                                 const float* __restrict__ bias,
                                                 float* __restrict__ D2, int sD2) {
    __shared__ __nv_bfloat16 As[BM][ASTR];
    __shared__ __nv_bfloat16 Bs[BN][ASTR];
    int tid = threadIdx.x;
    int warp = tid >> 5, lane = tid & 31;
    int wm = warp >> 1, wn = warp & 1;       // 4(m) x 2(n) warps, 32x32 warp tile
    int g = lane >> 2, q = lane & 3;
    int m0 = blockIdx.x * BM, n0 = blockIdx.y * BN;

    float acc[2][4][4];
#pragma unroll
    for (int mt = 0; mt < 2; ++mt)
#pragma unroll
        for (int nt = 0; nt < 4; ++nt)
#pragma unroll
            for (int i = 0; i < 4; ++i) acc[mt][nt][i] = 0.f;

    int nch = (3 * Kpad) / BK;
    int segch = Kpad / BK;
    const __nv_bfloat16* hip = g_Ahi;
    const __nv_bfloat16* lop = g_Alo;

    for (int c = 0; c < nch; ++c) {
        int seg = c / segch, cc = c - seg * segch;
        const __nv_bfloat16* ap = (seg == 1) ? lop : hip;
        // A tile: 128 rows x 32 bf16 (64B/row = 4 x 16B); 512 xfers, 2/thread
#pragma unroll
        for (int i = tid; i < 512; i += 256) {
            int row = i >> 2, qq = i & 3;
            *(uint4*)&As[row][qq * 8] =
                *(const uint4*)&ap[(size_t)(m0 + row) * Kpad + cc * 32 + qq * 8];
        }
        // B tile: 64 rows x 32 bf16; 256 xfers, 1/thread
        {
            int row = tid >> 2, qq = tid & 3;
            *(uint4*)&Bs[row][qq * 8] =
                *(const uint4*)&Wx[(size_t)(n0 + row) * wRow + c * 32 + qq * 8];
        }
        __syncthreads();
#pragma unroll
        for (int ks = 0; ks < 2; ++ks) {
            int kb = ks * 16;
            uint32_t a[2][4], b[4][2];
#pragma unroll
            for (int mt = 0; mt < 2; ++mt) {
                int mr = wm * 32 + mt * 16;
                a[mt][0] = *(const uint32_t*)&As[mr + g][kb + 2 * q];
                a[mt][1] = *(const uint32_t*)&As[mr + g + 8][kb + 2 * q];
                a[mt][2] = *(const uint32_t*)&As[mr + g][kb + 2 * q + 8];
                a[mt][3] = *(const uint32_t*)&As[mr + g + 8][kb + 2 * q + 8];
            }
#pragma unroll
            for (int nt = 0; nt < 4; ++nt) {
                int nc = wn * 32 + nt * 8 + g;
                b[nt][0] = *(const uint32_t*)&Bs[nc][kb + 2 * q];
                b[nt][1] = *(const uint32_t*)&Bs[nc][kb + 2 * q + 8];
            }
#pragma unroll
            for (int mt = 0; mt < 2; ++mt)
#pragma unroll
                for (int nt = 0; nt < 4; ++nt) mma_bf16(acc[mt][nt], a[mt], b[nt]);
        }
        __syncthreads();
    }
    // epilogue: c0:(g,2q) c1:(g,2q+1) c2:(g+8,2q) c3:(g+8,2q+1)
#pragma unroll
    for (int mt = 0; mt < 2; ++mt) {
#pragma unroll
        for (int nt = 0; nt < 4; ++nt) {
#pragma unroll
            for (int i = 0; i < 4; ++i) {
                int gm = m0 + wm * 32 + mt * 16 + g + ((i >> 1) ? 8 : 0);
                int gn = n0 + wn * 32 + nt * 8 + q * 2 + (i & 1);
                if (gm >= NN || gn >= Cout) continue;
                float r = acc[mt][nt][i];
                if (MODE == 0) {
                    D[(size_t)gm * sD + gn] = r;
                } else if (MODE == 1) {
                    D[(size_t)gm * sD + gn] += r;
                } else {
                    float v = D[(size_t)gm * sD + gn] + r + bias[gn];
                    D2[(size_t)gm * sD2 + gn] = fmaxf(v, 0.f);
                }
            }
        }
    }
}

// ---------------- layer 1 (Cin=1) ----------------
__global__ void __launch_bounds__(256) k_l1_out0(const float* __restrict__ x,
                                                 const float* __restrict__ W0,
                                                 const float* __restrict__ b) {
    int w = (blockIdx.x * 256 + threadIdx.x) >> 5;
    if (w >= NN) return;
    int lane = threadIdx.x & 31;
    float xv = x[w];
    g_AC[(size_t)w * 64 + lane] = xv * W0[lane] + b[lane];
    int c = lane + 32;
    if (c < 60) g_AC[(size_t)w * 64 + c] = xv * W0[c] + b[c];
}
__global__ void __launch_bounds__(256) k_l1_step(const float* __restrict__ hold,
                                                 float* __restrict__ hnew,
                                                 const float* __restrict__ Wk) {
    int w = (blockIdx.x * 256 + threadIdx.x) >> 5;
    if (w >= NN) return;
    int lane = threadIdx.x & 31;
    int beg = g_rowptr[w], end = g_rowptr[w + 1];
    float s = 0.f;
    for (int p = beg + lane; p < end; p += 32) {
        float2 cv = __ldg(&g_cv[p]);
        s += cv.y * __ldg(&hold[__float_as_int(cv.x)]);
    }
#pragma unroll
    for (int o = 16; o; o >>= 1) s += __shfl_xor_sync(0xffffffffu, s, o);
    if (lane == 0) hnew[w] = s;
    g_AC[(size_t)w * 64 + lane] += s * Wk[lane];
    int c = lane + 32;
    if (c < 60) g_AC[(size_t)w * 64 + c] += s * Wk[c];
}

// ---------------- layer 5 (Cout=1) ----------------
__global__ void __launch_bounds__(256) k_l5(const float* __restrict__ X,
                                            const float* __restrict__ Wk,
                                            const float* __restrict__ told,
                                            float* __restrict__ tnew, int first) {
    int w = (blockIdx.x * 256 + threadIdx.x) >> 5;
    if (w >= NN) return;
    int lane = threadIdx.x & 31;
    float s = 0.f;
    if (!first) {
        int beg = g_rowptr[w], end = g_rowptr[w + 1];
        for (int p = beg + lane; p < end; p += 32) {
            float2 cv = __ldg(&g_cv[p]);
            s += cv.y * __ldg(&told[__float_as_int(cv.x)]);
        }
    }
    const float* xr = X + (size_t)w * 96;
    s += xr[lane] * Wk[lane] + xr[lane + 32] * Wk[lane + 32];
    if (lane < 16) s += xr[lane + 64] * Wk[lane + 64];
#pragma unroll
    for (int o = 16; o; o >>= 1) s += __shfl_xor_sync(0xffffffffu, s, o);
    if (lane == 0) tnew[w] = s;
}

// ---------------- misc ----------------
__global__ void __launch_bounds__(256) k_relu(const float* __restrict__ src, int si,
                                              float* __restrict__ dst, int so, int C) {
    int w = (blockIdx.x * 256 + threadIdx.x) >> 5;
    if (w >= NN) return;
    int lane = threadIdx.x & 31;
    for (int c = lane; c < C; c += 32)
        dst[(size_t)w * so + c] = fmaxf(src[(size_t)w * si + c], 0.f);
}
__global__ void k_sigmoid(const float* __restrict__ t, const float* __restrict__ b,
                          float* __restrict__ out) {
    int i = blockIdx.x * blockDim.x + threadIdx.x;
    if (i < NN) out[i] = 1.f / (1.f + expf(-(t[i] + b[0])));
}

// ---------------- host ----------------
extern "C" void kernel_launch(void* const* d_in, const int* in_sizes, int n_in,
                              void* d_out, int out_size) {
    const float* x  = (const float*)d_in[0];
    const int*   ei = (const int*)d_in[1];
    const float* ew = (const float*)d_in[2];
    const float* Wl[5]; const float* bl[5];
    for (int l = 0; l < 5; ++l) {
        Wl[l] = (const float*)d_in[3 + 2 * l];
        bl[l] = (const float*)d_in[4 + 2 * l];
    }
    float* out = (float*)d_out;

    float *XL, *A0, *A1, *AC;
    __nv_bfloat16* Wexp;
    cudaGetSymbolAddress((void**)&XL, g_XL);
    cudaGetSymbolAddress((void**)&A0, g_A0);
    cudaGetSymbolAddress((void**)&A1, g_A1);
    cudaGetSymbolAddress((void**)&AC, g_AC);
    cudaGetSymbolAddress((void**)&Wexp, g_Wexp);

    const int WG = (NN * 32 + 255) / 256;
    const int GM = RPAD / 128;                    // 392 m-blocks

    // Wexp offsets/strides (elems)
    const size_t O2 = 0;
    const size_t H2 = 128 * 192;   // L2: Npad128, 3Kpad=192
    const size_t O3 = 516096;
    const size_t H3 = 256 * 384;   // L3: Npad256, 3Kpad=384
    const size_t O4 = 2580480;
    const size_t H4 = 128 * 768;   // L4: Npad128, 3Kpad=768

    // ---- CSR build ----
    k_zero_nodes<<<(NN + 255) / 256, 256>>>();
    k_degcnt<<<(EE + 255) / 256, 256>>>(ei, ew);
    k_dis<<<(NN + 255) / 256, 256>>>();
    k_bsum<<<SBLK, 256>>>();
    k_bscan<<<1, 256>>>();
    k_wptr<<<SBLK, 256>>>();
    k_scatter<<<(EE + 255) / 256, 256>>>(ei, ew);

    // ---- weight expansions ----
    k_wexp<<<(int)((21 * H2 + 255) / 256), 256>>>(Wl[1], 60, 100, 128, 64, Wexp + O2);
    k_wexp<<<(int)((21 * H3 + 255) / 256), 256>>>(Wl[2], 100, 200, 256, 128, Wexp + O3);
    k_wexp<<<(int)((21 * H4 + 255) / 256), 256>>>(Wl[3], 200, 80, 128, 256, Wexp + O4);

    // ---- layer 1 ----
    k_l1_out0<<<WG, 256>>>(x, Wl[0], bl[0]);
    {
        const float* hold = x;
        float* hnew = A0;
        for (int k = 1; k <= KH; ++k) {
            k_l1_step<<<WG, 256>>>(hold, hnew, Wl[0] + (size_t)k * 60);
            hold = hnew;
            hnew = (hnew == A0) ? A1 : A0;
        }
    }
    k_relu<<<WG, 256>>>(AC, 64, XL, 64, 60);

    // ---- layer 2: Kpad=64, Cout=100, grid.y=2 ----
    k_expand<<<(NN * 64 + 255) / 256, 256>>>(XL, 64, 64);
    {
        dim3 g(GM, 2);
        k_gemm_bf<0><<<g, 256>>>(64, Wexp + O2, 192, AC, 128, 100, 0, 0, 0);
        const float* hin = XL;
        float* hop = A0;
        for (int k = 1; k <= KH; ++k) {
            k_prop<2, true><<<WG, 256>>>(hin, hop);
            const __nv_bfloat16* Wk = Wexp + O2 + (size_t)k * H2;
            if (k < KH) k_gemm_bf<1><<<g, 256>>>(64, Wk, 192, AC, 128, 100, 0, 0, 0);
            else        k_gemm_bf<2><<<g, 256>>>(64, Wk, 192, AC, 128, 100,
                                                 bl[1], XL, 128);
            hin = hop;
            hop = (hop == A0) ? A1 : A0;
        }
    }

    // ---- layer 3: Kpad=128, Cout=200, grid.y=4 ----
    k_expand<<<(NN * 128 + 255) / 256, 256>>>(XL, 128, 128);
    {
        dim3 g(GM, 4);
        k_gemm_bf<0><<<g, 256>>>(128, Wexp + O3, 384, AC, 224, 200, 0, 0, 0);
        const float* hin = XL;
        float* hop = A0;
        for (int k = 1; k <= KH; ++k) {
            k_prop<4, true><<<WG, 256>>>(hin, hop);
            const __nv_bfloat16* Wk = Wexp + O3 + (size_t)k * H3;
            if (k < KH) k_gemm_bf<1><<<g, 256>>>(128, Wk, 384, AC, 224, 200, 0, 0, 0);
            else        k_gemm_bf<2><<<g, 256>>>(128, Wk, 384, AC, 224, 200,
                                                 bl[2], XL, 224);
            hin = hop;
            hop = (hop == A0) ? A1 : A0;
        }
    }

    // ---- layer 4: Kpad=256, Cout=80, grid.y=2; Horner output space ----
    k_expand<<<(NN * 256 + 255) / 256, 256>>>(XL, 224, 256);
    {
        dim3 g(GM, 2);
        float* t = A0;
        float* o = A1;
        k_gemm_bf<0><<<g, 256>>>(256, Wexp + O4 + (size_t)KH * H4, 768, t, 96, 80, 0, 0, 0);
        for (int k = KH - 1; k >= 1; --k) {
            k_prop<3, false><<<WG, 256>>>(t, o);
            k_gemm_bf<1><<<g, 256>>>(256, Wexp + O4 + (size_t)k * H4, 768, o, 96, 80, 0, 0, 0);
            float* tmp = t; t = o; o = tmp;
        }
        k_prop<3, false><<<WG, 256>>>(t, o);
        k_gemm_bf<2><<<g, 256>>>(256, Wexp + O4, 768, o, 96, 80, bl[3], AC, 96);
    }

    // ---- layer 5 ----
    {
        float* tA = A0;
        float* tB = A1;
        k_l5<<<WG, 256>>>(AC, Wl[4] + (size_t)KH * 80, 0, tA, 1);
        const float* hold = tA;
        float* cur = tB;
        float* nxt = tA;
        for (int k = KH - 1; k >= 0; --k) {
            k_l5<<<WG, 256>>>(AC, Wl[4] + (size_t)k * 80, hold, cur, 0);
            hold = cur;
            float* tmp = cur; cur = nxt; nxt = tmp;
        }
        k_sigmoid<<<(NN + 255) / 256, 256>>>(hold, bl[4], out);
    }
}

// round 12
// speedup vs baseline: 1.3219x; 1.3219x over previous
#include <cuda_runtime.h>
#include <cuda_bf16.h>
#include <cstdint>
#include <math.h>

#define NN 50000
#define RPAD 50176
#define EE 800000
#define KH 20
#define SBLK 196

// ---------------- scratch ----------------
__device__ float g_XL[(size_t)RPAD * 224];
__device__ float g_A0[(size_t)RPAD * 224];
__device__ float g_A1[(size_t)RPAD * 224];
__device__ float g_AC[(size_t)RPAD * 224];
__device__ __nv_bfloat16 g_Ahi[(size_t)RPAD * 256];
__device__ __nv_bfloat16 g_Alo[(size_t)RPAD * 256];
__device__ __nv_bfloat16 g_Wexp[4644864];
__device__ float  g_deg[NN];
__device__ float  g_dis[NN];
__device__ int    g_cnt[NN];
__device__ int    g_rowptr[NN + 1];
__device__ int    g_cursor[NN];
__device__ int    g_bsum[256];
__device__ int    g_boff[256];
__device__ float2 g_cv[EE];

// ---------------- bf16 mma helper ----------------
__device__ __forceinline__ void mma_bf16(float* c, const uint32_t* a, const uint32_t* b) {
    asm volatile(
        "mma.sync.aligned.m16n8k16.row.col.f32.bf16.bf16.f32 "
        "{%0,%1,%2,%3}, {%4,%5,%6,%7}, {%8,%9}, {%0,%1,%2,%3};"
        : "+f"(c[0]), "+f"(c[1]), "+f"(c[2]), "+f"(c[3])
        : "r"(a[0]), "r"(a[1]), "r"(a[2]), "r"(a[3]), "r"(b[0]), "r"(b[1]));
}

// ---------------- CSR build ----------------
__global__ void k_zero_nodes() {
    int i = blockIdx.x * blockDim.x + threadIdx.x;
    if (i < NN) { g_deg[i] = 0.f; g_cnt[i] = 0; }
}
__global__ void k_degcnt(const int* __restrict__ ei, const float* __restrict__ ew) {
    int e = blockIdx.x * blockDim.x + threadIdx.x;
    if (e < EE) {
        int d = ei[EE + e];
        atomicAdd(&g_deg[d], ew[e]);
        atomicAdd(&g_cnt[d], 1);
    }
}
__global__ void k_dis() {
    int i = blockIdx.x * blockDim.x + threadIdx.x;
    if (i < NN) {
        float d = g_deg[i];
        g_dis[i] = (d > 0.f) ? rsqrtf(d) : 0.f;
    }
}
__global__ void k_bsum() {
    __shared__ int sh[256];
    int t = threadIdx.x, i = blockIdx.x * 256 + t;
    sh[t] = (i < NN) ? g_cnt[i] : 0;
    __syncthreads();
    for (int o = 128; o; o >>= 1) {
        if (t < o) sh[t] += sh[t + o];
        __syncthreads();
    }
    if (!t) g_bsum[blockIdx.x] = sh[0];
}
__global__ void k_bscan() {
    __shared__ int sh[256];
    int t = threadIdx.x;
    int v = (t < SBLK) ? g_bsum[t] : 0;
    sh[t] = v;
    __syncthreads();
    for (int o = 1; o < 256; o <<= 1) {
        int u = (t >= o) ? sh[t - o] : 0;
        __syncthreads();
        sh[t] += u;
        __syncthreads();
    }
    if (t < SBLK) g_boff[t] = sh[t] - v;
}
__global__ void k_wptr() {
    __shared__ int sh[256];
    int t = threadIdx.x, i = blockIdx.x * 256 + t;
    int v = (i < NN) ? g_cnt[i] : 0;
    sh[t] = v;
    __syncthreads();
    for (int o = 1; o < 256; o <<= 1) {
        int u = (t >= o) ? sh[t - o] : 0;
        __syncthreads();
        sh[t] += u;
        __syncthreads();
    }
    int excl = sh[t] - v + g_boff[blockIdx.x];
    if (i < NN) {
        g_rowptr[i] = excl;
        g_cursor[i] = excl;
        if (i == NN - 1) g_rowptr[NN] = excl + v;
    }
}
__global__ void k_scatter(const int* __restrict__ ei, const float* __restrict__ ew) {
    int e = blockIdx.x * blockDim.x + threadIdx.x;
    if (e < EE) {
        int s = ei[e];
        int d = ei[EE + e];
        int p = atomicAdd(&g_cursor[d], 1);
        float2 cv;
        cv.x = __int_as_float(s);
        cv.y = g_dis[s] * ew[e] * g_dis[d];
        g_cv[p] = cv;
    }
}

// ---------------- propagation (optionally emits bf16 hi/lo planes) ------------
template <int CH, bool PL>
__global__ void __launch_bounds__(256) k_prop(const float* __restrict__ hin,
                                              float* __restrict__ hout) {
    int w = (blockIdx.x * 256 + threadIdx.x) >> 5;
    if (w >= NN) return;
    int lane = threadIdx.x & 31;
    int beg = g_rowptr[w], end = g_rowptr[w + 1];
    const int S = CH * 32;
    float acc[CH];
#pragma unroll
    for (int t = 0; t < CH; ++t) acc[t] = 0.f;
    int p = beg;
    for (; p + 2 <= end; p += 2) {
        float2 cv0 = __ldg(&g_cv[p]);
        float2 cv1 = __ldg(&g_cv[p + 1]);
        const float* r0 = hin + (size_t)__float_as_int(cv0.x) * S + lane;
        const float* r1 = hin + (size_t)__float_as_int(cv1.x) * S + lane;
#pragma unroll
        for (int t = 0; t < CH; ++t) acc[t] += cv0.y * __ldg(r0 + 32 * t);
#pragma unroll
        for (int t = 0; t < CH; ++t) acc[t] += cv1.y * __ldg(r1 + 32 * t);
    }
    if (p < end) {
        float2 cv = __ldg(&g_cv[p]);
        const float* r = hin + (size_t)__float_as_int(cv.x) * S + lane;
#pragma unroll
        for (int t = 0; t < CH; ++t) acc[t] += cv.y * __ldg(r + 32 * t);
    }
    float* o = hout + (size_t)w * S + lane;
#pragma unroll
    for (int t = 0; t < CH; ++t) {
        o[32 * t] = acc[t];
        if (PL) {
            __nv_bfloat16 h = __float2bfloat16(acc[t]);
            size_t idx = (size_t)w * S + 32 * t + lane;
            g_Ahi[idx] = h;
            g_Alo[idx] = __float2bfloat16(acc[t] - __bfloat162float(h));
        }
    }
}

// ---------------- expand fp32 activations into hi/lo planes ------------------
__global__ void k_expand(const float* __restrict__ src, int sX, int Kpad) {
    int idx = blockIdx.x * 256 + threadIdx.x;
    if (idx >= NN * Kpad) return;
    int w = idx / Kpad, c = idx - w * Kpad;
    float v = src[(size_t)w * sX + c];   // tail-col over-read: finite garbage, W rows are 0
    __nv_bfloat16 h = __float2bfloat16(v);
    g_Ahi[idx] = h;
    g_Alo[idx] = __float2bfloat16(v - __bfloat162float(h));
}

// ---------------- expand weights: [21,Cin,Cout] -> [21][Npad][2*Kpad] bf16 ----
// Row n holds k-contiguous [W_hi(:,n) | W_hi(:,n)] pairing A segments [hi | lo].
__global__ void k_wexp(const float* __restrict__ W, int Cin, int Cout,
                       int Npad, int Kpad, __nv_bfloat16* __restrict__ dst) {
    int idx = blockIdx.x * 256 + threadIdx.x;
    int per = Npad * 2 * Kpad;
    if (idx >= 21 * per) return;
    int k = idx / per;
    int r = idx - k * per;
    int n = r / (2 * Kpad);
    int j = r - n * 2 * Kpad;
    int ki = (j >= Kpad) ? (j - Kpad) : j;
    float v = (n < Cout && ki < Cin)
                  ? __ldg(&W[(size_t)k * Cin * Cout + (size_t)ki * Cout + n]) : 0.f;
    dst[idx] = __float2bfloat16(v);
}

// ---------------- bf16 tensor GEMM: 128 x (16*NT) tile, m16n8k16, 2-term -----
// MODE 0: D = P   MODE 1: D += P   MODE 2: D2 = relu(D + P + bias)
#define ASTR 40
template <int NT, int MODE>
__global__ void __launch_bounds__(256) k_gemm_bf(int Kpad,
                                                 const __nv_bfloat16* __restrict__ Wx,
                                                 int wRow,
                                                 float* __restrict__ D, int sD, int Cout,
                                                 const float* __restrict__ bias,
                                                 float* __restrict__ D2, int sD2) {
    const int BN = 16 * NT;
    __shared__ __nv_bfloat16 As[128][ASTR];
    __shared__ __nv_bfloat16 Bs[BN][ASTR];
    int tid = threadIdx.x;
    int warp = tid >> 5, lane = tid & 31;
    int wm = warp >> 1, wn = warp & 1;       // 4(m) x 2(n) warps
    int g = lane >> 2, q = lane & 3;
    int m0 = blockIdx.x * 128, n0 = blockIdx.y * BN;

    float acc[2][NT][4];
#pragma unroll
    for (int mt = 0; mt < 2; ++mt)
#pragma unroll
        for (int nt = 0; nt < NT; ++nt)
#pragma unroll
            for (int i = 0; i < 4; ++i) acc[mt][nt][i] = 0.f;

    int segch = Kpad >> 5;      // 32-wide chunks per K-segment
    int nch = 2 * segch;

    for (int c = 0; c < nch; ++c) {
        int seg = c / segch, cc = c - seg * segch;
        const __nv_bfloat16* ap = seg ? g_Alo : g_Ahi;
        // A tile: 128 rows x 32 bf16; 512 vec4 xfers
#pragma unroll
        for (int i = tid; i < 512; i += 256) {
            int row = i >> 2, qq = i & 3;
            *(uint4*)&As[row][qq * 8] =
                *(const uint4*)&ap[(size_t)(m0 + row) * Kpad + cc * 32 + qq * 8];
        }
        // B tile: BN rows x 32 bf16; BN*4 vec4 xfers
        for (int i = tid; i < BN * 4; i += 256) {
            int row = i >> 2, qq = i & 3;
            *(uint4*)&Bs[row][qq * 8] =
                *(const uint4*)&Wx[(size_t)(n0 + row) * wRow + c * 32 + qq * 8];
        }
        __syncthreads();
#pragma unroll
        for (int ks = 0; ks < 2; ++ks) {
            int kb = ks * 16;
            uint32_t a[2][4], b[NT][2];
#pragma unroll
            for (int mt = 0; mt < 2; ++mt) {
                int mr = wm * 32 + mt * 16;
                a[mt][0] = *(const uint32_t*)&As[mr + g][kb + 2 * q];
                a[mt][1] = *(const uint32_t*)&As[mr + g + 8][kb + 2 * q];
                a[mt][2] = *(const uint32_t*)&As[mr + g][kb + 2 * q + 8];
                a[mt][3] = *(const uint32_t*)&As[mr + g + 8][kb + 2 * q + 8];
            }
#pragma unroll
            for (int nt = 0; nt < NT; ++nt) {
                int nc = wn * (8 * NT) + nt * 8 + g;
                b[nt][0] = *(const uint32_t*)&Bs[nc][kb + 2 * q];
                b[nt][1] = *(const uint32_t*)&Bs[nc][kb + 2 * q + 8];
            }
#pragma unroll
            for (int mt = 0; mt < 2; ++mt)
#pragma unroll
                for (int nt = 0; nt < NT; ++nt) mma_bf16(acc[mt][nt], a[mt], b[nt]);
        }
        __syncthreads();
    }
    // epilogue: c0:(g,2q) c1:(g,2q+1) c2:(g+8,2q) c3:(g+8,2q+1)
#pragma unroll
    for (int mt = 0; mt < 2; ++mt) {
#pragma unroll
        for (int nt = 0; nt < NT; ++nt) {
#pragma unroll
            for (int i = 0; i < 4; ++i) {
                int gm = m0 + wm * 32 + mt * 16 + g + ((i >> 1) ? 8 : 0);
                int gn = n0 + wn * (8 * NT) + nt * 8 + q * 2 + (i & 1);
                if (gm >= NN || gn >= Cout) continue;
                float r = acc[mt][nt][i];
                if (MODE == 0) {
                    D[(size_t)gm * sD + gn] = r;
                } else if (MODE == 1) {
                    D[(size_t)gm * sD + gn] += r;
                } else {
                    float v = D[(size_t)gm * sD + gn] + r + bias[gn];
                    D2[(size_t)gm * sD2 + gn] = fmaxf(v, 0.f);
                }
            }
        }
    }
}

// ---------------- layer 1 (Cin=1) ----------------
__global__ void __launch_bounds__(256) k_l1_out0(const float* __restrict__ x,
                                                 const float* __restrict__ W0,
                                                 const float* __restrict__ b) {
    int w = (blockIdx.x * 256 + threadIdx.x) >> 5;
    if (w >= NN) return;
    int lane = threadIdx.x & 31;
    float xv = x[w];
    g_AC[(size_t)w * 64 + lane] = xv * W0[lane] + b[lane];
    int c = lane + 32;
    if (c < 60) g_AC[(size_t)w * 64 + c] = xv * W0[c] + b[c];
}
__global__ void __launch_bounds__(256) k_l1_step(const float* __restrict__ hold,
                                                 float* __restrict__ hnew,
                                                 const float* __restrict__ Wk) {
    int w = (blockIdx.x * 256 + threadIdx.x) >> 5;
    if (w >= NN) return;
    int lane = threadIdx.x & 31;
    int beg = g_rowptr[w], end = g_rowptr[w + 1];
    float s = 0.f;
    for (int p = beg + lane; p < end; p += 32) {
        float2 cv = __ldg(&g_cv[p]);
        s += cv.y * __ldg(&hold[__float_as_int(cv.x)]);
    }
#pragma unroll
    for (int o = 16; o; o >>= 1) s += __shfl_xor_sync(0xffffffffu, s, o);
    if (lane == 0) hnew[w] = s;
    g_AC[(size_t)w * 64 + lane] += s * Wk[lane];
    int c = lane + 32;
    if (c < 60) g_AC[(size_t)w * 64 + c] += s * Wk[c];
}

// ---------------- layer 5 (Cout=1) ----------------
__global__ void __launch_bounds__(256) k_l5(const float* __restrict__ X,
                                            const float* __restrict__ Wk,
                                            const float* __restrict__ told,
                                            float* __restrict__ tnew, int first) {
    int w = (blockIdx.x * 256 + threadIdx.x) >> 5;
    if (w >= NN) return;
    int lane = threadIdx.x & 31;
    float s = 0.f;
    if (!first) {
        int beg = g_rowptr[w], end = g_rowptr[w + 1];
        for (int p = beg + lane; p < end; p += 32) {
            float2 cv = __ldg(&g_cv[p]);
            s += cv.y * __ldg(&told[__float_as_int(cv.x)]);
        }
    }
    const float* xr = X + (size_t)w * 96;
    s += xr[lane] * Wk[lane] + xr[lane + 32] * Wk[lane + 32];
    if (lane < 16) s += xr[lane + 64] * Wk[lane + 64];
#pragma unroll
    for (int o = 16; o; o >>= 1) s += __shfl_xor_sync(0xffffffffu, s, o);
    if (lane == 0) tnew[w] = s;
}

// ---------------- misc ----------------
__global__ void __launch_bounds__(256) k_relu(const float* __restrict__ src, int si,
                                              float* __restrict__ dst, int so, int C) {
    int w = (blockIdx.x * 256 + threadIdx.x) >> 5;
    if (w >= NN) return;
    int lane = threadIdx.x & 31;
    for (int c = lane; c < C; c += 32)
        dst[(size_t)w * so + c] = fmaxf(src[(size_t)w * si + c], 0.f);
}
__global__ void k_sigmoid(const float* __restrict__ t, const float* __restrict__ b,
                          float* __restrict__ out) {
    int i = blockIdx.x * blockDim.x + threadIdx.x;
    if (i < NN) out[i] = 1.f / (1.f + expf(-(t[i] + b[0])));
}

// ---------------- host ----------------
extern "C" void kernel_launch(void* const* d_in, const int* in_sizes, int n_in,
                              void* d_out, int out_size) {
    const float* x  = (const float*)d_in[0];
    const int*   ei = (const int*)d_in[1];
    const float* ew = (const float*)d_in[2];
    const float* Wl[5]; const float* bl[5];
    for (int l = 0; l < 5; ++l) {
        Wl[l] = (const float*)d_in[3 + 2 * l];
        bl[l] = (const float*)d_in[4 + 2 * l];
    }
    float* out = (float*)d_out;

    float *XL, *A0, *A1, *AC;
    __nv_bfloat16* Wexp;
    cudaGetSymbolAddress((void**)&XL, g_XL);
    cudaGetSymbolAddress((void**)&A0, g_A0);
    cudaGetSymbolAddress((void**)&A1, g_A1);
    cudaGetSymbolAddress((void**)&AC, g_AC);
    cudaGetSymbolAddress((void**)&Wexp, g_Wexp);

    const int WG = (NN * 32 + 255) / 256;
    const int GM = RPAD / 128;                    // 392 m-blocks

    // Wexp offsets/strides (elems). rows = Npad, row len = 2*Kpad
    const size_t H2 = 112 * 128;  // L2: Npad112, 2Kpad=128
    const size_t O2 = 0;
    const size_t H3 = 224 * 256;  // L3: Npad224, 2Kpad=256
    const size_t O3 = O2 + 21 * H2;
    const size_t H4 = 80 * 448;   // L4: Npad80,  2Kpad=448
    const size_t O4 = O3 + 21 * H3;

    // ---- CSR build ----
    k_zero_nodes<<<(NN + 255) / 256, 256>>>();
    k_degcnt<<<(EE + 255) / 256, 256>>>(ei, ew);
    k_dis<<<(NN + 255) / 256, 256>>>();
    k_bsum<<<SBLK, 256>>>();
    k_bscan<<<1, 256>>>();
    k_wptr<<<SBLK, 256>>>();
    k_scatter<<<(EE + 255) / 256, 256>>>(ei, ew);

    // ---- weight expansions ----
    k_wexp<<<(int)((21 * H2 + 255) / 256), 256>>>(Wl[1], 60, 100, 112, 64, Wexp + O2);
    k_wexp<<<(int)((21 * H3 + 255) / 256), 256>>>(Wl[2], 100, 200, 224, 128, Wexp + O3);
    k_wexp<<<(int)((21 * H4 + 255) / 256), 256>>>(Wl[3], 200, 80, 80, 224, Wexp + O4);

    // ---- layer 1 ----
    k_l1_out0<<<WG, 256>>>(x, Wl[0], bl[0]);
    {
        const float* hold = x;
        float* hnew = A0;
        for (int k = 1; k <= KH; ++k) {
            k_l1_step<<<WG, 256>>>(hold, hnew, Wl[0] + (size_t)k * 60);
            hold = hnew;
            hnew = (hnew == A0) ? A1 : A0;
        }
    }
    k_relu<<<WG, 256>>>(AC, 64, XL, 64, 60);

    // ---- layer 2: Kpad=64, Cout=100, NT=7 (BN=112), grid.y=1 ----
    k_expand<<<(NN * 64 + 255) / 256, 256>>>(XL, 64, 64);
    {
        dim3 g(GM, 1);
        k_gemm_bf<7, 0><<<g, 256>>>(64, Wexp + O2, 128, AC, 128, 100, 0, 0, 0);
        const float* hin = XL;
        float* hop = A0;
        for (int k = 1; k <= KH; ++k) {
            k_prop<2, true><<<WG, 256>>>(hin, hop);
            const __nv_bfloat16* Wk = Wexp + O2 + (size_t)k * H2;
            if (k < KH) k_gemm_bf<7, 1><<<g, 256>>>(64, Wk, 128, AC, 128, 100, 0, 0, 0);
            else        k_gemm_bf<7, 2><<<g, 256>>>(64, Wk, 128, AC, 128, 100,
                                                    bl[1], XL, 128);
            hin = hop;
            hop = (hop == A0) ? A1 : A0;
        }
    }

    // ---- layer 3: Kpad=128, Cout=200, NT=7 (BN=112), grid.y=2 ----
    k_expand<<<(NN * 128 + 255) / 256, 256>>>(XL, 128, 128);
    {
        dim3 g(GM, 2);
        k_gemm_bf<7, 0><<<g, 256>>>(128, Wexp + O3, 256, AC, 224, 200, 0, 0, 0);
        const float* hin = XL;
        float* hop = A0;
        for (int k = 1; k <= KH; ++k) {
            k_prop<4, true><<<WG, 256>>>(hin, hop);
            const __nv_bfloat16* Wk = Wexp + O3 + (size_t)k * H3;
            if (k < KH) k_gemm_bf<7, 1><<<g, 256>>>(128, Wk, 256, AC, 224, 200, 0, 0, 0);
            else        k_gemm_bf<7, 2><<<g, 256>>>(128, Wk, 256, AC, 224, 200,
                                                    bl[2], XL, 224);
            hin = hop;
            hop = (hop == A0) ? A1 : A0;
        }
    }

    // ---- layer 4: Kpad=224, Cout=80, NT=5 (BN=80), grid.y=1; Horner ----
    k_expand<<<(NN * 224 + 255) / 256, 256>>>(XL, 224, 224);
    {
        dim3 g(GM, 1);
        float* t = A0;
        float* o = A1;
        k_gemm_bf<5, 0><<<g, 256>>>(224, Wexp + O4 + (size_t)KH * H4, 448,
                                    t, 96, 80, 0, 0, 0);
        for (int k = KH - 1; k >= 1; --k) {
            k_prop<3, false><<<WG, 256>>>(t, o);
            k_gemm_bf<5, 1><<<g, 256>>>(224, Wexp + O4 + (size_t)k * H4, 448,
                                        o, 96, 80, 0, 0, 0);
            float* tmp = t; t = o; o = tmp;
        }
        k_prop<3, false><<<WG, 256>>>(t, o);
        k_gemm_bf<5, 2><<<g, 256>>>(224, Wexp + O4, 448, o, 96, 80, bl[3], AC, 96);
    }

    // ---- layer 5 ----
    {
        float* tA = A0;
        float* tB = A1;
        k_l5<<<WG, 256>>>(AC, Wl[4] + (size_t)KH * 80, 0, tA, 1);
        const float* hold = tA;
        float* cur = tB;
        float* nxt = tA;
        for (int k = KH - 1; k >= 0; --k) {
            k_l5<<<WG, 256>>>(AC, Wl[4] + (size_t)k * 80, hold, cur, 0);
            hold = cur;
            float* tmp = cur; cur = nxt; nxt = tmp;
        }
        k_sigmoid<<<(NN + 255) / 256, 256>>>(hold, bl[4], out);
    }
}

// round 13
// speedup vs baseline: 1.4753x; 1.1161x over previous
#include <cuda_runtime.h>
#include <cuda_bf16.h>
#include <cstdint>
#include <math.h>

#define NN 50000
#define RPAD 50176
#define EE 800000
#define KH 20
#define SBLK 196

// ---------------- scratch ----------------
__device__ float g_XL[(size_t)RPAD * 224];
__device__ float g_A0[(size_t)RPAD * 224];
__device__ float g_A1[(size_t)RPAD * 224];
__device__ float g_AC[(size_t)RPAD * 224];
__device__ __nv_bfloat16 g_Ahi[(size_t)RPAD * 256];   // two plane slots
__device__ __nv_bfloat16 g_Alo[(size_t)RPAD * 256];
__device__ __nv_bfloat16 g_Wexp[4644864];
__device__ float  g_deg[NN];
__device__ float  g_dis[NN];
__device__ int    g_cnt[NN];
__device__ int    g_rowptr[NN + 1];
__device__ int    g_cursor[NN];
__device__ int    g_bsum[256];
__device__ int    g_boff[256];
__device__ float2 g_cv[EE];

// ---------------- bf16 mma helper ----------------
__device__ __forceinline__ void mma_bf16(float* c, const uint32_t* a, const uint32_t* b) {
    asm volatile(
        "mma.sync.aligned.m16n8k16.row.col.f32.bf16.bf16.f32 "
        "{%0,%1,%2,%3}, {%4,%5,%6,%7}, {%8,%9}, {%0,%1,%2,%3};"
        : "+f"(c[0]), "+f"(c[1]), "+f"(c[2]), "+f"(c[3])
        : "r"(a[0]), "r"(a[1]), "r"(a[2]), "r"(a[3]), "r"(b[0]), "r"(b[1]));
}

// ---------------- CSR build ----------------
__global__ void k_zero_nodes() {
    int i = blockIdx.x * blockDim.x + threadIdx.x;
    if (i < NN) { g_deg[i] = 0.f; g_cnt[i] = 0; }
}
__global__ void k_degcnt(const int* __restrict__ ei, const float* __restrict__ ew) {
    int e = blockIdx.x * blockDim.x + threadIdx.x;
    if (e < EE) {
        int d = ei[EE + e];
        atomicAdd(&g_deg[d], ew[e]);
        atomicAdd(&g_cnt[d], 1);
    }
}
__global__ void k_dis() {
    int i = blockIdx.x * blockDim.x + threadIdx.x;
    if (i < NN) {
        float d = g_deg[i];
        g_dis[i] = (d > 0.f) ? rsqrtf(d) : 0.f;
    }
}
__global__ void k_bsum() {
    __shared__ int sh[256];
    int t = threadIdx.x, i = blockIdx.x * 256 + t;
    sh[t] = (i < NN) ? g_cnt[i] : 0;
    __syncthreads();
    for (int o = 128; o; o >>= 1) {
        if (t < o) sh[t] += sh[t + o];
        __syncthreads();
    }
    if (!t) g_bsum[blockIdx.x] = sh[0];
}
__global__ void k_bscan() {
    __shared__ int sh[256];
    int t = threadIdx.x;
    int v = (t < SBLK) ? g_bsum[t] : 0;
    sh[t] = v;
    __syncthreads();
    for (int o = 1; o < 256; o <<= 1) {
        int u = (t >= o) ? sh[t - o] : 0;
        __syncthreads();
        sh[t] += u;
        __syncthreads();
    }
    if (t < SBLK) g_boff[t] = sh[t] - v;
}
__global__ void k_wptr() {
    __shared__ int sh[256];
    int t = threadIdx.x, i = blockIdx.x * 256 + t;
    int v = (i < NN) ? g_cnt[i] : 0;
    sh[t] = v;
    __syncthreads();
    for (int o = 1; o < 256; o <<= 1) {
        int u = (t >= o) ? sh[t - o] : 0;
        __syncthreads();
        sh[t] += u;
        __syncthreads();
    }
    int excl = sh[t] - v + g_boff[blockIdx.x];
    if (i < NN) {
        g_rowptr[i] = excl;
        g_cursor[i] = excl;
        if (i == NN - 1) g_rowptr[NN] = excl + v;
    }
}
__global__ void k_scatter(const int* __restrict__ ei, const float* __restrict__ ew) {
    int e = blockIdx.x * blockDim.x + threadIdx.x;
    if (e < EE) {
        int s = ei[e];
        int d = ei[EE + e];
        int p = atomicAdd(&g_cursor[d], 1);
        float2 cv;
        cv.x = __int_as_float(s);
        cv.y = g_dis[s] * ew[e] * g_dis[d];
        g_cv[p] = cv;
    }
}

// ---------------- vectorized propagation kernels ----------------
// CH=2 (S=64): lane owns channels {2l, 2l+1}; optional bf16 plane emission.
template <bool PL>
__global__ void __launch_bounds__(256) k_prop2(const float* __restrict__ hin,
                                               float* __restrict__ hout,
                                               __nv_bfloat16* __restrict__ phi,
                                               __nv_bfloat16* __restrict__ plo) {
    int w = (blockIdx.x * 256 + threadIdx.x) >> 5;
    if (w >= NN) return;
    int lane = threadIdx.x & 31;
    int beg = g_rowptr[w], end = g_rowptr[w + 1];
    float2 acc = make_float2(0.f, 0.f);
    int p = beg;
    for (; p + 2 <= end; p += 2) {
        float2 cv0 = __ldg(&g_cv[p]);
        float2 cv1 = __ldg(&g_cv[p + 1]);
        float2 v0 = __ldg((const float2*)(hin + (size_t)__float_as_int(cv0.x) * 64) + lane);
        float2 v1 = __ldg((const float2*)(hin + (size_t)__float_as_int(cv1.x) * 64) + lane);
        acc.x += cv0.y * v0.x + cv1.y * v1.x;
        acc.y += cv0.y * v0.y + cv1.y * v1.y;
    }
    if (p < end) {
        float2 cv = __ldg(&g_cv[p]);
        float2 v = __ldg((const float2*)(hin + (size_t)__float_as_int(cv.x) * 64) + lane);
        acc.x += cv.y * v.x;
        acc.y += cv.y * v.y;
    }
    *((float2*)(hout + (size_t)w * 64) + lane) = acc;
    if (PL) {
        __nv_bfloat162 h2 = __floats2bfloat162_rn(acc.x, acc.y);
        float rx = acc.x - __bfloat162float(h2.x);
        float ry = acc.y - __bfloat162float(h2.y);
        *((__nv_bfloat162*)(phi + (size_t)w * 64) + lane) = h2;
        *((__nv_bfloat162*)(plo + (size_t)w * 64) + lane) = __floats2bfloat162_rn(rx, ry);
    }
}
// CH=4 (S=128): lane owns channels {4l..4l+3}.
template <bool PL>
__global__ void __launch_bounds__(256) k_prop4(const float* __restrict__ hin,
                                               float* __restrict__ hout,
                                               __nv_bfloat16* __restrict__ phi,
                                               __nv_bfloat16* __restrict__ plo) {
    int w = (blockIdx.x * 256 + threadIdx.x) >> 5;
    if (w >= NN) return;
    int lane = threadIdx.x & 31;
    int beg = g_rowptr[w], end = g_rowptr[w + 1];
    float4 acc = make_float4(0.f, 0.f, 0.f, 0.f);
    int p = beg;
    for (; p + 2 <= end; p += 2) {
        float2 cv0 = __ldg(&g_cv[p]);
        float2 cv1 = __ldg(&g_cv[p + 1]);
        float4 v0 = __ldg((const float4*)(hin + (size_t)__float_as_int(cv0.x) * 128) + lane);
        float4 v1 = __ldg((const float4*)(hin + (size_t)__float_as_int(cv1.x) * 128) + lane);
        acc.x += cv0.y * v0.x + cv1.y * v1.x;
        acc.y += cv0.y * v0.y + cv1.y * v1.y;
        acc.z += cv0.y * v0.z + cv1.y * v1.z;
        acc.w += cv0.y * v0.w + cv1.y * v1.w;
    }
    if (p < end) {
        float2 cv = __ldg(&g_cv[p]);
        float4 v = __ldg((const float4*)(hin + (size_t)__float_as_int(cv.x) * 128) + lane);
        acc.x += cv.y * v.x; acc.y += cv.y * v.y;
        acc.z += cv.y * v.z; acc.w += cv.y * v.w;
    }
    *((float4*)(hout + (size_t)w * 128) + lane) = acc;
    if (PL) {
        __nv_bfloat162 h0 = __floats2bfloat162_rn(acc.x, acc.y);
        __nv_bfloat162 h1 = __floats2bfloat162_rn(acc.z, acc.w);
        __nv_bfloat162 l0 = __floats2bfloat162_rn(acc.x - __bfloat162float(h0.x),
                                                  acc.y - __bfloat162float(h0.y));
        __nv_bfloat162 l1 = __floats2bfloat162_rn(acc.z - __bfloat162float(h1.x),
                                                  acc.w - __bfloat162float(h1.y));
        *((__nv_bfloat162*)(phi + (size_t)w * 128) + 2 * lane)     = h0;
        *((__nv_bfloat162*)(phi + (size_t)w * 128) + 2 * lane + 1) = h1;
        *((__nv_bfloat162*)(plo + (size_t)w * 128) + 2 * lane)     = l0;
        *((__nv_bfloat162*)(plo + (size_t)w * 128) + 2 * lane + 1) = l1;
    }
}
// CH=3 (S=96): lane owns {2l,2l+1} and {64+l}; no planes needed.
__global__ void __launch_bounds__(256) k_prop3(const float* __restrict__ hin,
                                               float* __restrict__ hout) {
    int w = (blockIdx.x * 256 + threadIdx.x) >> 5;
    if (w >= NN) return;
    int lane = threadIdx.x & 31;
    int beg = g_rowptr[w], end = g_rowptr[w + 1];
    float2 acc = make_float2(0.f, 0.f);
    float acc1 = 0.f;
    int p = beg;
    for (; p + 2 <= end; p += 2) {
        float2 cv0 = __ldg(&g_cv[p]);
        float2 cv1 = __ldg(&g_cv[p + 1]);
        const float* r0 = hin + (size_t)__float_as_int(cv0.x) * 96;
        const float* r1 = hin + (size_t)__float_as_int(cv1.x) * 96;
        float2 v0 = __ldg((const float2*)r0 + lane);
        float2 v1 = __ldg((const float2*)r1 + lane);
        float s0 = __ldg(r0 + 64 + lane);
        float s1 = __ldg(r1 + 64 + lane);
        acc.x += cv0.y * v0.x + cv1.y * v1.x;
        acc.y += cv0.y * v0.y + cv1.y * v1.y;
        acc1 += cv0.y * s0 + cv1.y * s1;
    }
    if (p < end) {
        float2 cv = __ldg(&g_cv[p]);
        const float* r = hin + (size_t)__float_as_int(cv.x) * 96;
        float2 v = __ldg((const float2*)r + lane);
        acc.x += cv.y * v.x;
        acc.y += cv.y * v.y;
        acc1 += cv.y * __ldg(r + 64 + lane);
    }
    *((float2*)(hout + (size_t)w * 96) + lane) = acc;
    hout[(size_t)w * 96 + 64 + lane] = acc1;
}

// ---------------- scalar propagation (Horner step with add) ------------------
template <bool ADD>
__global__ void __launch_bounds__(256) k_sprop(const float* __restrict__ hold,
                                               float* __restrict__ hnew,
                                               const float* __restrict__ addp) {
    int w = (blockIdx.x * 256 + threadIdx.x) >> 5;
    if (w >= NN) return;
    int lane = threadIdx.x & 31;
    int beg = g_rowptr[w], end = g_rowptr[w + 1];
    float s = 0.f;
    for (int p = beg + lane; p < end; p += 32) {
        float2 cv = __ldg(&g_cv[p]);
        s += cv.y * __ldg(&hold[__float_as_int(cv.x)]);
    }
#pragma unroll
    for (int o = 16; o; o >>= 1) s += __shfl_xor_sync(0xffffffffu, s, o);
    if (lane == 0) hnew[w] = ADD ? (s + addp[w]) : s;
}

// ---------------- expand fp32 activations into bf16 hi/lo planes -------------
__global__ void k_expand(const float* __restrict__ src, int sX, int Kpad,
                         __nv_bfloat16* __restrict__ phi, __nv_bfloat16* __restrict__ plo) {
    int idx = blockIdx.x * 256 + threadIdx.x;
    if (idx >= NN * Kpad) return;
    int w = idx / Kpad, c = idx - w * Kpad;
    float v = src[(size_t)w * sX + c];
    __nv_bfloat16 h = __float2bfloat16(v);
    phi[idx] = h;
    plo[idx] = __float2bfloat16(v - __bfloat162float(h));
}

// ---------------- expand weights: [21,Cin,Cout] -> [21][Npad][2*Kpad] bf16 ----
__global__ void k_wexp(const float* __restrict__ W, int Cin, int Cout,
                       int Npad, int Kpad, __nv_bfloat16* __restrict__ dst) {
    int idx = blockIdx.x * 256 + threadIdx.x;
    int per = Npad * 2 * Kpad;
    if (idx >= 21 * per) return;
    int k = idx / per;
    int r = idx - k * per;
    int n = r / (2 * Kpad);
    int j = r - n * 2 * Kpad;
    int ki = (j >= Kpad) ? (j - Kpad) : j;
    float v = (n < Cout && ki < Cin)
                  ? __ldg(&W[(size_t)k * Cin * Cout + (size_t)ki * Cout + n]) : 0.f;
    dst[idx] = __float2bfloat16(v);
}

// ---------------- bf16 tensor GEMM: 128 x (16*NT), m16n8k16, NH hop sources --
// MODE 0: D = P   MODE 1: D += P   MODE 2: D2 = relu(D + P + bias)
// P = sum_h [Ahi_h | Alo_h] @ [W_h; W_h]  (2-term split, hop planes at h*slotOff)
#define ASTR 40
template <int NT, int MODE, int NH>
__global__ void __launch_bounds__(256) k_gemm_bf(int Kpad, size_t slotOff,
                                                 const __nv_bfloat16* __restrict__ Wx,
                                                 int wRow, size_t wStep,
                                                 float* __restrict__ D, int sD, int Cout,
                                                 const float* __restrict__ bias,
                                                 float* __restrict__ D2, int sD2) {
    const int BN = 16 * NT;
    __shared__ __nv_bfloat16 As[128][ASTR];
    __shared__ __nv_bfloat16 Bs[BN][ASTR];
    int tid = threadIdx.x;
    int warp = tid >> 5, lane = tid & 31;
    int wm = warp >> 1, wn = warp & 1;
    int g = lane >> 2, q = lane & 3;
    int m0 = blockIdx.x * 128, n0 = blockIdx.y * BN;

    float acc[2][NT][4];
#pragma unroll
    for (int mt = 0; mt < 2; ++mt)
#pragma unroll
        for (int nt = 0; nt < NT; ++nt)
#pragma unroll
            for (int i = 0; i < 4; ++i) acc[mt][nt][i] = 0.f;

    int segch = Kpad >> 5;
    int nch = 2 * segch;

#pragma unroll
    for (int h = 0; h < NH; ++h) {
        const __nv_bfloat16* hip = g_Ahi + (size_t)h * slotOff;
        const __nv_bfloat16* lop = g_Alo + (size_t)h * slotOff;
        const __nv_bfloat16* Wh = Wx + (size_t)h * wStep;
        for (int c = 0; c < nch; ++c) {
            int seg = c / segch, cc = c - seg * segch;
            const __nv_bfloat16* ap = seg ? lop : hip;
#pragma unroll
            for (int i = tid; i < 512; i += 256) {
                int row = i >> 2, qq = i & 3;
                *(uint4*)&As[row][qq * 8] =
                    *(const uint4*)&ap[(size_t)(m0 + row) * Kpad + cc * 32 + qq * 8];
            }
            for (int i = tid; i < BN * 4; i += 256) {
                int row = i >> 2, qq = i & 3;
                *(uint4*)&Bs[row][qq * 8] =
                    *(const uint4*)&Wh[(size_t)(n0 + row) * wRow + c * 32 + qq * 8];
            }
            __syncthreads();
#pragma unroll
            for (int ks = 0; ks < 2; ++ks) {
                int kb = ks * 16;
                uint32_t a[2][4], b[NT][2];
#pragma unroll
                for (int mt = 0; mt < 2; ++mt) {
                    int mr = wm * 32 + mt * 16;
                    a[mt][0] = *(const uint32_t*)&As[mr + g][kb + 2 * q];
                    a[mt][1] = *(const uint32_t*)&As[mr + g + 8][kb + 2 * q];
                    a[mt][2] = *(const uint32_t*)&As[mr + g][kb + 2 * q + 8];
                    a[mt][3] = *(const uint32_t*)&As[mr + g + 8][kb + 2 * q + 8];
                }
#pragma unroll
                for (int nt = 0; nt < NT; ++nt) {
                    int nc = wn * (8 * NT) + nt * 8 + g;
                    b[nt][0] = *(const uint32_t*)&Bs[nc][kb + 2 * q];
                    b[nt][1] = *(const uint32_t*)&Bs[nc][kb + 2 * q + 8];
                }
#pragma unroll
                for (int mt = 0; mt < 2; ++mt)
#pragma unroll
                    for (int nt = 0; nt < NT; ++nt) mma_bf16(acc[mt][nt], a[mt], b[nt]);
            }
            __syncthreads();
        }
    }
#pragma unroll
    for (int mt = 0; mt < 2; ++mt) {
#pragma unroll
        for (int nt = 0; nt < NT; ++nt) {
#pragma unroll
            for (int i = 0; i < 4; ++i) {
                int gm = m0 + wm * 32 + mt * 16 + g + ((i >> 1) ? 8 : 0);
                int gn = n0 + wn * (8 * NT) + nt * 8 + q * 2 + (i & 1);
                if (gm >= NN || gn >= Cout) continue;
                float r = acc[mt][nt][i];
                if (MODE == 0) {
                    D[(size_t)gm * sD + gn] = r;
                } else if (MODE == 1) {
                    D[(size_t)gm * sD + gn] += r;
                } else {
                    float v = D[(size_t)gm * sD + gn] + r + bias[gn];
                    D2[(size_t)gm * sD2 + gn] = fmaxf(v, 0.f);
                }
            }
        }
    }
}

// ---------------- layer 1 (Cin=1) ----------------
__global__ void __launch_bounds__(256) k_l1_out0(const float* __restrict__ x,
                                                 const float* __restrict__ W0,
                                                 const float* __restrict__ b) {
    int w = (blockIdx.x * 256 + threadIdx.x) >> 5;
    if (w >= NN) return;
    int lane = threadIdx.x & 31;
    float xv = x[w];
    g_AC[(size_t)w * 64 + lane] = xv * W0[lane] + b[lane];
    int c = lane + 32;
    if (c < 60) g_AC[(size_t)w * 64 + c] = xv * W0[c] + b[c];
}
__global__ void __launch_bounds__(256) k_l1_step(const float* __restrict__ hold,
                                                 float* __restrict__ hnew,
                                                 const float* __restrict__ Wk) {
    int w = (blockIdx.x * 256 + threadIdx.x) >> 5;
    if (w >= NN) return;
    int lane = threadIdx.x & 31;
    int beg = g_rowptr[w], end = g_rowptr[w + 1];
    float s = 0.f;
    for (int p = beg + lane; p < end; p += 32) {
        float2 cv = __ldg(&g_cv[p]);
        s += cv.y * __ldg(&hold[__float_as_int(cv.x)]);
    }
#pragma unroll
    for (int o = 16; o; o >>= 1) s += __shfl_xor_sync(0xffffffffu, s, o);
    if (lane == 0) hnew[w] = s;
    g_AC[(size_t)w * 64 + lane] += s * Wk[lane];
    int c = lane + 32;
    if (c < 60) g_AC[(size_t)w * 64 + c] += s * Wk[c];
}

// ---------------- layer 5: Y[k][n] = X[n,:] . W5[k,:] (X stride 96) ----------
__global__ void __launch_bounds__(256) k_y5(const float* __restrict__ X,
                                            const float* __restrict__ W5,
                                            float* __restrict__ Y) {
    int w = (blockIdx.x * 256 + threadIdx.x) >> 5;
    if (w >= NN) return;
    int lane = threadIdx.x & 31;
    const float* xr = X + (size_t)w * 96;
    float x0 = xr[lane], x1 = xr[32 + lane];
    float x2 = (lane < 16) ? xr[64 + lane] : 0.f;
#pragma unroll
    for (int k = 0; k < 21; ++k) {
        float s = x0 * __ldg(&W5[k * 80 + lane]) + x1 * __ldg(&W5[k * 80 + 32 + lane]);
        if (lane < 16) s += x2 * __ldg(&W5[k * 80 + 64 + lane]);
#pragma unroll
        for (int o = 16; o; o >>= 1) s += __shfl_xor_sync(0xffffffffu, s, o);
        if (lane == 0) Y[(size_t)k * RPAD + w] = s;
    }
}

// ---------------- misc ----------------
__global__ void __launch_bounds__(256) k_relu(const float* __restrict__ src, int si,
                                              float* __restrict__ dst, int so, int C) {
    int w = (blockIdx.x * 256 + threadIdx.x) >> 5;
    if (w >= NN) return;
    int lane = threadIdx.x & 31;
    for (int c = lane; c < C; c += 32)
        dst[(size_t)w * so + c] = fmaxf(src[(size_t)w * si + c], 0.f);
}
__global__ void k_sigmoid(const float* __restrict__ t, const float* __restrict__ b,
                          float* __restrict__ out) {
    int i = blockIdx.x * blockDim.x + threadIdx.x;
    if (i < NN) out[i] = 1.f / (1.f + expf(-(t[i] + b[0])));
}

// ---------------- host ----------------
extern "C" void kernel_launch(void* const* d_in, const int* in_sizes, int n_in,
                              void* d_out, int out_size) {
    const float* x  = (const float*)d_in[0];
    const int*   ei = (const int*)d_in[1];
    const float* ew = (const float*)d_in[2];
    const float* Wl[5]; const float* bl[5];
    for (int l = 0; l < 5; ++l) {
        Wl[l] = (const float*)d_in[3 + 2 * l];
        bl[l] = (const float*)d_in[4 + 2 * l];
    }
    float* out = (float*)d_out;

    float *XL, *A0, *A1, *AC;
    __nv_bfloat16 *Wexp, *Ahi, *Alo;
    cudaGetSymbolAddress((void**)&XL, g_XL);
    cudaGetSymbolAddress((void**)&A0, g_A0);
    cudaGetSymbolAddress((void**)&A1, g_A1);
    cudaGetSymbolAddress((void**)&AC, g_AC);
    cudaGetSymbolAddress((void**)&Wexp, g_Wexp);
    cudaGetSymbolAddress((void**)&Ahi, g_Ahi);
    cudaGetSymbolAddress((void**)&Alo, g_Alo);

    const int WG = (NN * 32 + 255) / 256;
    const int GM = RPAD / 128;

    const size_t H2 = 112 * 128;
    const size_t O2 = 0;
    const size_t H3 = 224 * 256;
    const size_t O3 = O2 + 21 * H2;
    const size_t H4 = 80 * 448;
    const size_t O4 = O3 + 21 * H3;

    // ---- CSR build ----
    k_zero_nodes<<<(NN + 255) / 256, 256>>>();
    k_degcnt<<<(EE + 255) / 256, 256>>>(ei, ew);
    k_dis<<<(NN + 255) / 256, 256>>>();
    k_bsum<<<SBLK, 256>>>();
    k_bscan<<<1, 256>>>();
    k_wptr<<<SBLK, 256>>>();
    k_scatter<<<(EE + 255) / 256, 256>>>(ei, ew);

    // ---- weight expansions ----
    k_wexp<<<(int)((21 * H2 + 255) / 256), 256>>>(Wl[1], 60, 100, 112, 64, Wexp + O2);
    k_wexp<<<(int)((21 * H3 + 255) / 256), 256>>>(Wl[2], 100, 200, 224, 128, Wexp + O3);
    k_wexp<<<(int)((21 * H4 + 255) / 256), 256>>>(Wl[3], 200, 80, 80, 224, Wexp + O4);

    // ---- layer 1 ----
    k_l1_out0<<<WG, 256>>>(x, Wl[0], bl[0]);
    {
        const float* hold = x;
        float* hnew = A0;
        for (int k = 1; k <= KH; ++k) {
            k_l1_step<<<WG, 256>>>(hold, hnew, Wl[0] + (size_t)k * 60);
            hold = hnew;
            hnew = (hnew == A0) ? A1 : A0;
        }
    }
    k_relu<<<WG, 256>>>(AC, 64, XL, 64, 60);

    // ---- layer 2: Kpad=64, Cout=100, NT=7, hop-paired ----
    {
        const size_t SL = (size_t)RPAD * 64;       // plane slot stride
        dim3 g(GM, 1);
        k_expand<<<(NN * 64 + 255) / 256, 256>>>(XL, 64, 64, Ahi, Alo);          // hop0 -> slot0
        k_prop2<true><<<WG, 256>>>(XL, A0, Ahi + SL, Alo + SL);                  // hop1 -> slot1
        k_gemm_bf<7, 0, 2><<<g, 256>>>(64, SL, Wexp + O2, 128, H2, AC, 128, 100, 0, 0, 0);
        for (int j = 1; j <= 9; ++j) {
            k_prop2<true><<<WG, 256>>>(A0, A1, Ahi, Alo);                        // hop 2j -> slot0
            k_prop2<true><<<WG, 256>>>(A1, A0, Ahi + SL, Alo + SL);              // hop 2j+1 -> slot1
            k_gemm_bf<7, 1, 2><<<g, 256>>>(64, SL, Wexp + O2 + (size_t)(2 * j) * H2, 128, H2,
                                           AC, 128, 100, 0, 0, 0);
        }
        k_prop2<true><<<WG, 256>>>(A0, A1, Ahi, Alo);                            // hop20 -> slot0
        k_gemm_bf<7, 2, 1><<<g, 256>>>(64, 0, Wexp + O2 + (size_t)KH * H2, 128, 0,
                                       AC, 128, 100, bl[1], XL, 128);
    }

    // ---- layer 3: Kpad=128, Cout=200, NT=7, grid.y=2, hop-paired ----
    {
        const size_t SL = (size_t)RPAD * 128;
        dim3 g(GM, 2);
        k_expand<<<(NN * 128 + 255) / 256, 256>>>(XL, 128, 128, Ahi, Alo);
        k_prop4<true><<<WG, 256>>>(XL, A0, Ahi + SL, Alo + SL);
        k_gemm_bf<7, 0, 2><<<g, 256>>>(128, SL, Wexp + O3, 256, H3, AC, 224, 200, 0, 0, 0);
        for (int j = 1; j <= 9; ++j) {
            k_prop4<true><<<WG, 256>>>(A0, A1, Ahi, Alo);
            k_prop4<true><<<WG, 256>>>(A1, A0, Ahi + SL, Alo + SL);
            k_gemm_bf<7, 1, 2><<<g, 256>>>(128, SL, Wexp + O3 + (size_t)(2 * j) * H3, 256, H3,
                                           AC, 224, 200, 0, 0, 0);
        }
        k_prop4<true><<<WG, 256>>>(A0, A1, Ahi, Alo);
        k_gemm_bf<7, 2, 1><<<g, 256>>>(128, 0, Wexp + O3 + (size_t)KH * H3, 256, 0,
                                       AC, 224, 200, bl[2], XL, 224);
    }

    // ---- layer 4: Kpad=224, Cout=80, NT=5; Horner, fixed A-planes ----
    k_expand<<<(NN * 224 + 255) / 256, 256>>>(XL, 224, 224, Ahi, Alo);
    {
        dim3 g(GM, 1);
        float* t = A0;
        float* o = A1;
        k_gemm_bf<5, 0, 1><<<g, 256>>>(224, 0, Wexp + O4 + (size_t)KH * H4, 448, 0,
                                       t, 96, 80, 0, 0, 0);
        for (int k = KH - 1; k >= 1; --k) {
            k_prop3<<<WG, 256>>>(t, o);
            k_gemm_bf<5, 1, 1><<<g, 256>>>(224, 0, Wexp + O4 + (size_t)k * H4, 448, 0,
                                           o, 96, 80, 0, 0, 0);
            float* tmp = t; t = o; o = tmp;
        }
        k_prop3<<<WG, 256>>>(t, o);
        k_gemm_bf<5, 2, 1><<<g, 256>>>(224, 0, Wexp + O4, 448, 0, o, 96, 80, bl[3], AC, 96);
    }

    // ---- layer 5: Y-stack (in XL) then scalar Horner ----
    k_y5<<<WG, 256>>>(AC, Wl[4], XL);
    {
        const float* hold = XL + (size_t)KH * RPAD;   // Y20
        float* cur = A0;
        float* nxt = A1;
        for (int k = KH - 1; k >= 0; --k) {
            k_sprop<true><<<WG, 256>>>(hold, cur, XL + (size_t)k * RPAD);
            hold = cur;
            float* tmp = cur; cur = nxt; nxt = tmp;
        }
        k_sigmoid<<<(NN + 255) / 256, 256>>>(hold, bl[4], out);
    }
}

// round 14
// speedup vs baseline: 1.5314x; 1.0380x over previous
#include <cuda_runtime.h>
#include <cuda_bf16.h>
#include <cstdint>
#include <math.h>

#define NN 50000
#define RPAD 50176
#define EE 800000
#define KH 20
#define SBLK 196

// ---------------- scratch ----------------
__device__ float g_XL[(size_t)RPAD * 224];
__device__ float g_A0[(size_t)RPAD * 224];
__device__ float g_A1[(size_t)RPAD * 224];
__device__ float g_AC[(size_t)RPAD * 224];
__device__ __nv_bfloat16 g_Ahi[(size_t)RPAD * 512];   // 4 plane slots (L3: 4x128)
__device__ __nv_bfloat16 g_Alo[(size_t)RPAD * 512];
__device__ __nv_bfloat16 g_Wexp[4644864];
__device__ float  g_deg[NN];
__device__ float  g_dis[NN];
__device__ int    g_cnt[NN];
__device__ int    g_rowptr[NN + 1];
__device__ int    g_cursor[NN];
__device__ int    g_bsum[256];
__device__ int    g_boff[256];
__device__ float2 g_cv[EE];

// ---------------- bf16 mma helper ----------------
__device__ __forceinline__ void mma_bf16(float* c, const uint32_t* a, const uint32_t* b) {
    asm volatile(
        "mma.sync.aligned.m16n8k16.row.col.f32.bf16.bf16.f32 "
        "{%0,%1,%2,%3}, {%4,%5,%6,%7}, {%8,%9}, {%0,%1,%2,%3};"
        : "+f"(c[0]), "+f"(c[1]), "+f"(c[2]), "+f"(c[3])
        : "r"(a[0]), "r"(a[1]), "r"(a[2]), "r"(a[3]), "r"(b[0]), "r"(b[1]));
}

// ---------------- CSR build ----------------
__global__ void k_zero_nodes() {
    int i = blockIdx.x * blockDim.x + threadIdx.x;
    if (i < NN) { g_deg[i] = 0.f; g_cnt[i] = 0; }
}
__global__ void k_degcnt(const int* __restrict__ ei, const float* __restrict__ ew) {
    int e = blockIdx.x * blockDim.x + threadIdx.x;
    if (e < EE) {
        int d = ei[EE + e];
        atomicAdd(&g_deg[d], ew[e]);
        atomicAdd(&g_cnt[d], 1);
    }
}
__global__ void k_dis() {
    int i = blockIdx.x * blockDim.x + threadIdx.x;
    if (i < NN) {
        float d = g_deg[i];
        g_dis[i] = (d > 0.f) ? rsqrtf(d) : 0.f;
    }
}
__global__ void k_bsum() {
    __shared__ int sh[256];
    int t = threadIdx.x, i = blockIdx.x * 256 + t;
    sh[t] = (i < NN) ? g_cnt[i] : 0;
    __syncthreads();
    for (int o = 128; o; o >>= 1) {
        if (t < o) sh[t] += sh[t + o];
        __syncthreads();
    }
    if (!t) g_bsum[blockIdx.x] = sh[0];
}
__global__ void k_bscan() {
    __shared__ int sh[256];
    int t = threadIdx.x;
    int v = (t < SBLK) ? g_bsum[t] : 0;
    sh[t] = v;
    __syncthreads();
    for (int o = 1; o < 256; o <<= 1) {
        int u = (t >= o) ? sh[t - o] : 0;
        __syncthreads();
        sh[t] += u;
        __syncthreads();
    }
    if (t < SBLK) g_boff[t] = sh[t] - v;
}
__global__ void k_wptr() {
    __shared__ int sh[256];
    int t = threadIdx.x, i = blockIdx.x * 256 + t;
    int v = (i < NN) ? g_cnt[i] : 0;
    sh[t] = v;
    __syncthreads();
    for (int o = 1; o < 256; o <<= 1) {
        int u = (t >= o) ? sh[t - o] : 0;
        __syncthreads();
        sh[t] += u;
        __syncthreads();
    }
    int excl = sh[t] - v + g_boff[blockIdx.x];
    if (i < NN) {
        g_rowptr[i] = excl;
        g_cursor[i] = excl;
        if (i == NN - 1) g_rowptr[NN] = excl + v;
    }
}
__global__ void k_scatter(const int* __restrict__ ei, const float* __restrict__ ew) {
    int e = blockIdx.x * blockDim.x + threadIdx.x;
    if (e < EE) {
        int s = ei[e];
        int d = ei[EE + e];
        int p = atomicAdd(&g_cursor[d], 1);
        float2 cv;
        cv.x = __int_as_float(s);
        cv.y = g_dis[s] * ew[e] * g_dis[d];
        g_cv[p] = cv;
    }
}

// ---------------- vectorized propagation kernels ----------------
template <bool PL>
__global__ void __launch_bounds__(256) k_prop2(const float* __restrict__ hin,
                                               float* __restrict__ hout,
                                               __nv_bfloat16* __restrict__ phi,
                                               __nv_bfloat16* __restrict__ plo) {
    int w = (blockIdx.x * 256 + threadIdx.x) >> 5;
    if (w >= NN) return;
    int lane = threadIdx.x & 31;
    int beg = g_rowptr[w], end = g_rowptr[w + 1];
    float2 acc = make_float2(0.f, 0.f);
    int p = beg;
    for (; p + 2 <= end; p += 2) {
        float2 cv0 = __ldg(&g_cv[p]);
        float2 cv1 = __ldg(&g_cv[p + 1]);
        float2 v0 = __ldg((const float2*)(hin + (size_t)__float_as_int(cv0.x) * 64) + lane);
        float2 v1 = __ldg((const float2*)(hin + (size_t)__float_as_int(cv1.x) * 64) + lane);
        acc.x += cv0.y * v0.x + cv1.y * v1.x;
        acc.y += cv0.y * v0.y + cv1.y * v1.y;
    }
    if (p < end) {
        float2 cv = __ldg(&g_cv[p]);
        float2 v = __ldg((const float2*)(hin + (size_t)__float_as_int(cv.x) * 64) + lane);
        acc.x += cv.y * v.x;
        acc.y += cv.y * v.y;
    }
    *((float2*)(hout + (size_t)w * 64) + lane) = acc;
    if (PL) {
        __nv_bfloat162 h2 = __floats2bfloat162_rn(acc.x, acc.y);
        float rx = acc.x - __bfloat162float(h2.x);
        float ry = acc.y - __bfloat162float(h2.y);
        *((__nv_bfloat162*)(phi + (size_t)w * 64) + lane) = h2;
        *((__nv_bfloat162*)(plo + (size_t)w * 64) + lane) = __floats2bfloat162_rn(rx, ry);
    }
}
template <bool PL>
__global__ void __launch_bounds__(256) k_prop4(const float* __restrict__ hin,
                                               float* __restrict__ hout,
                                               __nv_bfloat16* __restrict__ phi,
                                               __nv_bfloat16* __restrict__ plo) {
    int w = (blockIdx.x * 256 + threadIdx.x) >> 5;
    if (w >= NN) return;
    int lane = threadIdx.x & 31;
    int beg = g_rowptr[w], end = g_rowptr[w + 1];
    float4 acc = make_float4(0.f, 0.f, 0.f, 0.f);
    int p = beg;
    for (; p + 2 <= end; p += 2) {
        float2 cv0 = __ldg(&g_cv[p]);
        float2 cv1 = __ldg(&g_cv[p + 1]);
        float4 v0 = __ldg((const float4*)(hin + (size_t)__float_as_int(cv0.x) * 128) + lane);
        float4 v1 = __ldg((const float4*)(hin + (size_t)__float_as_int(cv1.x) * 128) + lane);
        acc.x += cv0.y * v0.x + cv1.y * v1.x;
        acc.y += cv0.y * v0.y + cv1.y * v1.y;
        acc.z += cv0.y * v0.z + cv1.y * v1.z;
        acc.w += cv0.y * v0.w + cv1.y * v1.w;
    }
    if (p < end) {
        float2 cv = __ldg(&g_cv[p]);
        float4 v = __ldg((const float4*)(hin + (size_t)__float_as_int(cv.x) * 128) + lane);
        acc.x += cv.y * v.x; acc.y += cv.y * v.y;
        acc.z += cv.y * v.z; acc.w += cv.y * v.w;
    }
    *((float4*)(hout + (size_t)w * 128) + lane) = acc;
    if (PL) {
        __nv_bfloat162 h0 = __floats2bfloat162_rn(acc.x, acc.y);
        __nv_bfloat162 h1 = __floats2bfloat162_rn(acc.z, acc.w);
        __nv_bfloat162 l0 = __floats2bfloat162_rn(acc.x - __bfloat162float(h0.x),
                                                  acc.y - __bfloat162float(h0.y));
        __nv_bfloat162 l1 = __floats2bfloat162_rn(acc.z - __bfloat162float(h1.x),
                                                  acc.w - __bfloat162float(h1.y));
        *((__nv_bfloat162*)(phi + (size_t)w * 128) + 2 * lane)     = h0;
        *((__nv_bfloat162*)(phi + (size_t)w * 128) + 2 * lane + 1) = h1;
        *((__nv_bfloat162*)(plo + (size_t)w * 128) + 2 * lane)     = l0;
        *((__nv_bfloat162*)(plo + (size_t)w * 128) + 2 * lane + 1) = l1;
    }
}
__global__ void __launch_bounds__(256) k_prop3(const float* __restrict__ hin,
                                               float* __restrict__ hout) {
    int w = (blockIdx.x * 256 + threadIdx.x) >> 5;
    if (w >= NN) return;
    int lane = threadIdx.x & 31;
    int beg = g_rowptr[w], end = g_rowptr[w + 1];
    float2 acc = make_float2(0.f, 0.f);
    float acc1 = 0.f;
    int p = beg;
    for (; p + 2 <= end; p += 2) {
        float2 cv0 = __ldg(&g_cv[p]);
        float2 cv1 = __ldg(&g_cv[p + 1]);
        const float* r0 = hin + (size_t)__float_as_int(cv0.x) * 96;
        const float* r1 = hin + (size_t)__float_as_int(cv1.x) * 96;
        float2 v0 = __ldg((const float2*)r0 + lane);
        float2 v1 = __ldg((const float2*)r1 + lane);
        float s0 = __ldg(r0 + 64 + lane);
        float s1 = __ldg(r1 + 64 + lane);
        acc.x += cv0.y * v0.x + cv1.y * v1.x;
        acc.y += cv0.y * v0.y + cv1.y * v1.y;
        acc1 += cv0.y * s0 + cv1.y * s1;
    }
    if (p < end) {
        float2 cv = __ldg(&g_cv[p]);
        const float* r = hin + (size_t)__float_as_int(cv.x) * 96;
        float2 v = __ldg((const float2*)r + lane);
        acc.x += cv.y * v.x;
        acc.y += cv.y * v.y;
        acc1 += cv.y * __ldg(r + 64 + lane);
    }
    *((float2*)(hout + (size_t)w * 96) + lane) = acc;
    hout[(size_t)w * 96 + 64 + lane] = acc1;
}

// ---------------- scalar propagation ----------------
template <bool ADD>
__global__ void __launch_bounds__(256) k_sprop(const float* __restrict__ hold,
                                               float* __restrict__ hnew,
                                               const float* __restrict__ addp) {
    int w = (blockIdx.x * 256 + threadIdx.x) >> 5;
    if (w >= NN) return;
    int lane = threadIdx.x & 31;
    int beg = g_rowptr[w], end = g_rowptr[w + 1];
    float s = 0.f;
    for (int p = beg + lane; p < end; p += 32) {
        float2 cv = __ldg(&g_cv[p]);
        s += cv.y * __ldg(&hold[__float_as_int(cv.x)]);
    }
#pragma unroll
    for (int o = 16; o; o >>= 1) s += __shfl_xor_sync(0xffffffffu, s, o);
    if (lane == 0) hnew[w] = ADD ? (s + addp[w]) : s;
}
__global__ void k_copy(const float* __restrict__ src, float* __restrict__ dst) {
    int i = blockIdx.x * blockDim.x + threadIdx.x;
    if (i < NN) dst[i] = src[i];
}

// ---------------- expand fp32 activations into bf16 hi/lo planes -------------
__global__ void k_expand(const float* __restrict__ src, int sX, int Kpad,
                         __nv_bfloat16* __restrict__ phi, __nv_bfloat16* __restrict__ plo) {
    int idx = blockIdx.x * 256 + threadIdx.x;
    if (idx >= NN * Kpad) return;
    int w = idx / Kpad, c = idx - w * Kpad;
    float v = src[(size_t)w * sX + c];
    __nv_bfloat16 h = __float2bfloat16(v);
    phi[idx] = h;
    plo[idx] = __float2bfloat16(v - __bfloat162float(h));
}

// ---------------- expand weights ----------------
__global__ void k_wexp(const float* __restrict__ W, int Cin, int Cout,
                       int Npad, int Kpad, __nv_bfloat16* __restrict__ dst) {
    int idx = blockIdx.x * 256 + threadIdx.x;
    int per = Npad * 2 * Kpad;
    if (idx >= 21 * per) return;
    int k = idx / per;
    int r = idx - k * per;
    int n = r / (2 * Kpad);
    int j = r - n * 2 * Kpad;
    int ki = (j >= Kpad) ? (j - Kpad) : j;
    float v = (n < Cout && ki < Cin)
                  ? __ldg(&W[(size_t)k * Cin * Cout + (size_t)ki * Cout + n]) : 0.f;
    dst[idx] = __float2bfloat16(v);
}

// ---------------- bf16 tensor GEMM ----------------
#define ASTR 40
template <int NT, int MODE, int NH>
__global__ void __launch_bounds__(256) k_gemm_bf(int Kpad, size_t abase, size_t slotOff,
                                                 const __nv_bfloat16* __restrict__ Wx,
                                                 int wRow, size_t wStep,
                                                 float* __restrict__ D, int sD, int Cout,
                                                 const float* __restrict__ bias,
                                                 float* __restrict__ D2, int sD2) {
    const int BN = 16 * NT;
    __shared__ __nv_bfloat16 As[128][ASTR];
    __shared__ __nv_bfloat16 Bs[BN][ASTR];
    int tid = threadIdx.x;
    int warp = tid >> 5, lane = tid & 31;
    int wm = warp >> 1, wn = warp & 1;
    int g = lane >> 2, q = lane & 3;
    int m0 = blockIdx.x * 128, n0 = blockIdx.y * BN;

    float acc[2][NT][4];
#pragma unroll
    for (int mt = 0; mt < 2; ++mt)
#pragma unroll
        for (int nt = 0; nt < NT; ++nt)
#pragma unroll
            for (int i = 0; i < 4; ++i) acc[mt][nt][i] = 0.f;

    int segch = Kpad >> 5;
    int nch = 2 * segch;

#pragma unroll
    for (int h = 0; h < NH; ++h) {
        const __nv_bfloat16* hip = g_Ahi + abase + (size_t)h * slotOff;
        const __nv_bfloat16* lop = g_Alo + abase + (size_t)h * slotOff;
        const __nv_bfloat16* Wh = Wx + (size_t)h * wStep;
        for (int c = 0; c < nch; ++c) {
            int seg = c / segch, cc = c - seg * segch;
            const __nv_bfloat16* ap = seg ? lop : hip;
#pragma unroll
            for (int i = tid; i < 512; i += 256) {
                int row = i >> 2, qq = i & 3;
                *(uint4*)&As[row][qq * 8] =
                    *(const uint4*)&ap[(size_t)(m0 + row) * Kpad + cc * 32 + qq * 8];
            }
            for (int i = tid; i < BN * 4; i += 256) {
                int row = i >> 2, qq = i & 3;
                *(uint4*)&Bs[row][qq * 8] =
                    *(const uint4*)&Wh[(size_t)(n0 + row) * wRow + c * 32 + qq * 8];
            }
            __syncthreads();
#pragma unroll
            for (int ks = 0; ks < 2; ++ks) {
                int kb = ks * 16;
                uint32_t a[2][4], b[NT][2];
#pragma unroll
                for (int mt = 0; mt < 2; ++mt) {
                    int mr = wm * 32 + mt * 16;
                    a[mt][0] = *(const uint32_t*)&As[mr + g][kb + 2 * q];
                    a[mt][1] = *(const uint32_t*)&As[mr + g + 8][kb + 2 * q];
                    a[mt][2] = *(const uint32_t*)&As[mr + g][kb + 2 * q + 8];
                    a[mt][3] = *(const uint32_t*)&As[mr + g + 8][kb + 2 * q + 8];
                }
#pragma unroll
                for (int nt = 0; nt < NT; ++nt) {
                    int nc = wn * (8 * NT) + nt * 8 + g;
                    b[nt][0] = *(const uint32_t*)&Bs[nc][kb + 2 * q];
                    b[nt][1] = *(const uint32_t*)&Bs[nc][kb + 2 * q + 8];
                }
#pragma unroll
                for (int mt = 0; mt < 2; ++mt)
#pragma unroll
                    for (int nt = 0; nt < NT; ++nt) mma_bf16(acc[mt][nt], a[mt], b[nt]);
            }
            __syncthreads();
        }
    }
#pragma unroll
    for (int mt = 0; mt < 2; ++mt) {
#pragma unroll
        for (int nt = 0; nt < NT; ++nt) {
#pragma unroll
            for (int i = 0; i < 4; ++i) {
                int gm = m0 + wm * 32 + mt * 16 + g + ((i >> 1) ? 8 : 0);
                int gn = n0 + wn * (8 * NT) + nt * 8 + q * 2 + (i & 1);
                if (gm >= NN || gn >= Cout) continue;
                float r = acc[mt][nt][i];
                if (MODE == 0) {
                    D[(size_t)gm * sD + gn] = r;
                } else if (MODE == 1) {
                    D[(size_t)gm * sD + gn] += r;
                } else {
                    float v = D[(size_t)gm * sD + gn] + r + bias[gn];
                    D2[(size_t)gm * sD2 + gn] = fmaxf(v, 0.f);
                }
            }
        }
    }
}

// ---------------- layer 1 head: XL = relu(stack(A^k x) @ W1 + b1) -------------
__global__ void __launch_bounds__(256) k_head(const float* __restrict__ S,
                                              const float* __restrict__ W1,
                                              const float* __restrict__ b1) {
    int w = (blockIdx.x * 256 + threadIdx.x) >> 5;
    if (w >= NN) return;
    int lane = threadIdx.x & 31;
    float xk[21];
#pragma unroll
    for (int k = 0; k < 21; ++k) xk[k] = __ldg(&S[(size_t)k * RPAD + w]);
    for (int c = lane; c < 60; c += 32) {
        float a = b1[c];
#pragma unroll
        for (int k = 0; k < 21; ++k) a += xk[k] * __ldg(&W1[k * 60 + c]);
        g_XL[(size_t)w * 64 + c] = fmaxf(a, 0.f);
    }
}

// ---------------- layer 5: Y[k][n] = X[n,:] . W5[k,:] ----------------
__global__ void __launch_bounds__(256) k_y5(const float* __restrict__ X,
                                            const float* __restrict__ W5,
                                            float* __restrict__ Y) {
    int w = (blockIdx.x * 256 + threadIdx.x) >> 5;
    if (w >= NN) return;
    int lane = threadIdx.x & 31;
    const float* xr = X + (size_t)w * 96;
    float x0 = xr[lane], x1 = xr[32 + lane];
    float x2 = (lane < 16) ? xr[64 + lane] : 0.f;
#pragma unroll
    for (int k = 0; k < 21; ++k) {
        float s = x0 * __ldg(&W5[k * 80 + lane]) + x1 * __ldg(&W5[k * 80 + 32 + lane]);
        if (lane < 16) s += x2 * __ldg(&W5[k * 80 + 64 + lane]);
#pragma unroll
        for (int o = 16; o; o >>= 1) s += __shfl_xor_sync(0xffffffffu, s, o);
        if (lane == 0) Y[(size_t)k * RPAD + w] = s;
    }
}

__global__ void k_sigmoid(const float* __restrict__ t, const float* __restrict__ b,
                          float* __restrict__ out) {
    int i = blockIdx.x * blockDim.x + threadIdx.x;
    if (i < NN) out[i] = 1.f / (1.f + expf(-(t[i] + b[0])));
}

// ---------------- host ----------------
extern "C" void kernel_launch(void* const* d_in, const int* in_sizes, int n_in,
                              void* d_out, int out_size) {
    const float* x  = (const float*)d_in[0];
    const int*   ei = (const int*)d_in[1];
    const float* ew = (const float*)d_in[2];
    const float* Wl[5]; const float* bl[5];
    for (int l = 0; l < 5; ++l) {
        Wl[l] = (const float*)d_in[3 + 2 * l];
        bl[l] = (const float*)d_in[4 + 2 * l];
    }
    float* out = (float*)d_out;

    float *XL, *A0, *A1, *AC;
    __nv_bfloat16 *Wexp, *Ahi, *Alo;
    cudaGetSymbolAddress((void**)&XL, g_XL);
    cudaGetSymbolAddress((void**)&A0, g_A0);
    cudaGetSymbolAddress((void**)&A1, g_A1);
    cudaGetSymbolAddress((void**)&AC, g_AC);
    cudaGetSymbolAddress((void**)&Wexp, g_Wexp);
    cudaGetSymbolAddress((void**)&Ahi, g_Ahi);
    cudaGetSymbolAddress((void**)&Alo, g_Alo);

    const int WG = (NN * 32 + 255) / 256;
    const int GM = RPAD / 128;

    const size_t H2 = 112 * 128;
    const size_t O2 = 0;
    const size_t H3 = 224 * 256;
    const size_t O3 = O2 + 21 * H2;
    const size_t H4 = 80 * 448;
    const size_t O4 = O3 + 21 * H3;

    // second stream + events (fork-join; leak — only 2 host calls total)
    cudaStream_t s2;
    cudaStreamCreateWithFlags(&s2, cudaStreamNonBlocking);
    cudaEvent_t ep[22], eg[22];
    for (int i = 0; i < 22; ++i) {
        cudaEventCreateWithFlags(&ep[i], cudaEventDisableTiming);
        cudaEventCreateWithFlags(&eg[i], cudaEventDisableTiming);
    }

    // ---- CSR build ----
    k_zero_nodes<<<(NN + 255) / 256, 256>>>();
    k_degcnt<<<(EE + 255) / 256, 256>>>(ei, ew);
    k_dis<<<(NN + 255) / 256, 256>>>();
    k_bsum<<<SBLK, 256>>>();
    k_bscan<<<1, 256>>>();
    k_wptr<<<SBLK, 256>>>();
    k_scatter<<<(EE + 255) / 256, 256>>>(ei, ew);

    // ---- weight expansions ----
    k_wexp<<<(int)((21 * H2 + 255) / 256), 256>>>(Wl[1], 60, 100, 112, 64, Wexp + O2);
    k_wexp<<<(int)((21 * H3 + 255) / 256), 256>>>(Wl[2], 100, 200, 224, 128, Wexp + O3);
    k_wexp<<<(int)((21 * H4 + 255) / 256), 256>>>(Wl[3], 200, 80, 80, 224, Wexp + O4);

    // ---- layer 1: scalar hop stack in A0, fused head GEMV ----
    k_copy<<<(NN + 255) / 256, 256>>>(x, A0);
    for (int k = 1; k <= KH; ++k)
        k_sprop<false><<<WG, 256>>>(A0 + (size_t)(k - 1) * RPAD, A0 + (size_t)k * RPAD, 0);
    k_head<<<WG, 256>>>(A0, Wl[0], bl[0]);

    // ---- layer 2: Kpad=64, Cout=100, NT=7, hop-paired, overlapped ----
    {
        const size_t SL = (size_t)RPAD * 64;
        dim3 g(GM, 1);
        k_expand<<<(NN * 64 + 255) / 256, 256>>>(XL, 64, 64, Ahi, Alo);     // slot0
        k_prop2<true><<<WG, 256>>>(XL, A0, Ahi + SL, Alo + SL);             // slot1
        cudaEventRecord(ep[0], 0);
        cudaStreamWaitEvent(s2, ep[0], 0);
        k_gemm_bf<7, 0, 2><<<g, 256, 0, s2>>>(64, 0, SL, Wexp + O2, 128, H2,
                                              AC, 128, 100, 0, 0, 0);
        cudaEventRecord(eg[0], s2);
        for (int j = 1; j <= 9; ++j) {
            size_t base = (j & 1) ? 2 * SL : 0;
            if (j >= 2) cudaStreamWaitEvent(0, eg[j - 2], 0);
            k_prop2<true><<<WG, 256>>>(A0, A1, Ahi + base, Alo + base);
            k_prop2<true><<<WG, 256>>>(A1, A0, Ahi + base + SL, Alo + base + SL);
            cudaEventRecord(ep[j], 0);
            cudaStreamWaitEvent(s2, ep[j], 0);
            k_gemm_bf<7, 1, 2><<<g, 256, 0, s2>>>(64, base, SL,
                                                  Wexp + O2 + (size_t)(2 * j) * H2, 128, H2,
                                                  AC, 128, 100, 0, 0, 0);
            cudaEventRecord(eg[j], s2);
        }
        cudaStreamWaitEvent(0, eg[8], 0);
        k_prop2<true><<<WG, 256>>>(A0, A1, Ahi, Alo);                       // hop20 slot0
        cudaEventRecord(ep[10], 0);
        cudaStreamWaitEvent(s2, ep[10], 0);
        k_gemm_bf<7, 2, 1><<<g, 256, 0, s2>>>(64, 0, 0, Wexp + O2 + (size_t)KH * H2, 128, 0,
                                              AC, 128, 100, bl[1], XL, 128);
        cudaEventRecord(eg[10], s2);
        cudaStreamWaitEvent(0, eg[10], 0);                                  // join
    }

    // ---- layer 3: Kpad=128, Cout=200, NT=7, grid.y=2, overlapped ----
    {
        const size_t SL = (size_t)RPAD * 128;
        dim3 g(GM, 2);
        k_expand<<<(NN * 128 + 255) / 256, 256>>>(XL, 128, 128, Ahi, Alo);
        k_prop4<true><<<WG, 256>>>(XL, A0, Ahi + SL, Alo + SL);
        cudaEventRecord(ep[11], 0);
        cudaStreamWaitEvent(s2, ep[11], 0);
        k_gemm_bf<7, 0, 2><<<g, 256, 0, s2>>>(128, 0, SL, Wexp + O3, 256, H3,
                                              AC, 224, 200, 0, 0, 0);
        cudaEventRecord(eg[11], s2);
        for (int j = 1; j <= 9; ++j) {
            size_t base = (j & 1) ? 2 * SL : 0;
            if (j >= 2) cudaStreamWaitEvent(0, eg[11 + j - 2], 0);
            k_prop4<true><<<WG, 256>>>(A0, A1, Ahi + base, Alo + base);
            k_prop4<true><<<WG, 256>>>(A1, A0, Ahi + base + SL, Alo + base + SL);
            cudaEventRecord(ep[11 + j], 0);
            cudaStreamWaitEvent(s2, ep[11 + j], 0);
            k_gemm_bf<7, 1, 2><<<g, 256, 0, s2>>>(128, base, SL,
                                                  Wexp + O3 + (size_t)(2 * j) * H3, 256, H3,
                                                  AC, 224, 200, 0, 0, 0);
            cudaEventRecord(eg[11 + j], s2);
        }
        cudaStreamWaitEvent(0, eg[11 + 8], 0);
        k_prop4<true><<<WG, 256>>>(A0, A1, Ahi, Alo);
        cudaEventRecord(ep[21], 0);
        cudaStreamWaitEvent(s2, ep[21], 0);
        k_gemm_bf<7, 2, 1><<<g, 256, 0, s2>>>(128, 0, 0, Wexp + O3 + (size_t)KH * H3, 256, 0,
                                              AC, 224, 200, bl[2], XL, 224);
        cudaEventRecord(eg[21], s2);
        cudaStreamWaitEvent(0, eg[21], 0);                                  // join
    }

    // ---- layer 4: Kpad=224, Cout=80, NT=5; serial Horner ----
    k_expand<<<(NN * 224 + 255) / 256, 256>>>(XL, 224, 224, Ahi, Alo);
    {
        dim3 g(GM, 1);
        float* t = A0;
        float* o = A1;
        k_gemm_bf<5, 0, 1><<<g, 256>>>(224, 0, 0, Wexp + O4 + (size_t)KH * H4, 448, 0,
                                       t, 96, 80, 0, 0, 0);
        for (int k = KH - 1; k >= 1; --k) {
            k_prop3<<<WG, 256>>>(t, o);
            k_gemm_bf<5, 1, 1><<<g, 256>>>(224, 0, 0, Wexp + O4 + (size_t)k * H4, 448, 0,
                                           o, 96, 80, 0, 0, 0);
            float* tmp = t; t = o; o = tmp;
        }
        k_prop3<<<WG, 256>>>(t, o);
        k_gemm_bf<5, 2, 1><<<g, 256>>>(224, 0, 0, Wexp + O4, 448, 0, o, 96, 80, bl[3], AC, 96);
    }

    // ---- layer 5: Y-stack in XL, scalar Horner ----
    k_y5<<<WG, 256>>>(AC, Wl[4], XL);
    {
        const float* hold = XL + (size_t)KH * RPAD;
        float* cur = A0;
        float* nxt = A1;
        for (int k = KH - 1; k >= 0; --k) {
            k_sprop<true><<<WG, 256>>>(hold, cur, XL + (size_t)k * RPAD);
            hold = cur;
            float* tmp = cur; cur = nxt; nxt = tmp;
        }
        k_sigmoid<<<(NN + 255) / 256, 256>>>(hold, bl[4], out);
    }
}

// round 15
// speedup vs baseline: 1.6076x; 1.0497x over previous
#include <cuda_runtime.h>
#include <cuda_bf16.h>
#include <cstdint>
#include <math.h>

#define NN 50000
#define RPAD 50176
#define EE 800000
#define KH 20
#define SBLK 196

// ---------------- scratch ----------------
__device__ float g_XL[(size_t)RPAD * 224];
__device__ float g_A0[(size_t)RPAD * 224];
__device__ float g_A1[(size_t)RPAD * 224];
__device__ float g_AC[(size_t)RPAD * 224];
__device__ __nv_bfloat16 g_Ahi[(size_t)RPAD * 512];   // 4 plane slots
__device__ __nv_bfloat16 g_Alo[(size_t)RPAD * 512];
__device__ __nv_bfloat16 g_Wexp[4644864];
__device__ float  g_deg[NN];
__device__ float  g_dis[NN];
__device__ int    g_cnt[NN];
__device__ int    g_rowptr[NN + 1];
__device__ int    g_cursor[NN];
__device__ int    g_bsum[256];
__device__ int    g_boff[256];
__device__ float2 g_cv[EE];

// ---------------- bf16 mma helper ----------------
__device__ __forceinline__ void mma_bf16(float* c, const uint32_t* a, const uint32_t* b) {
    asm volatile(
        "mma.sync.aligned.m16n8k16.row.col.f32.bf16.bf16.f32 "
        "{%0,%1,%2,%3}, {%4,%5,%6,%7}, {%8,%9}, {%0,%1,%2,%3};"
        : "+f"(c[0]), "+f"(c[1]), "+f"(c[2]), "+f"(c[3])
        : "r"(a[0]), "r"(a[1]), "r"(a[2]), "r"(a[3]), "r"(b[0]), "r"(b[1]));
}

// ---------------- CSR build ----------------
__global__ void k_zero_nodes() {
    int i = blockIdx.x * blockDim.x + threadIdx.x;
    if (i < NN) { g_deg[i] = 0.f; g_cnt[i] = 0; }
}
__global__ void k_degcnt(const int* __restrict__ ei, const float* __restrict__ ew) {
    int e = blockIdx.x * blockDim.x + threadIdx.x;
    if (e < EE) {
        int d = ei[EE + e];
        atomicAdd(&g_deg[d], ew[e]);
        atomicAdd(&g_cnt[d], 1);
    }
}
__global__ void k_dis() {
    int i = blockIdx.x * blockDim.x + threadIdx.x;
    if (i < NN) {
        float d = g_deg[i];
        g_dis[i] = (d > 0.f) ? rsqrtf(d) : 0.f;
    }
}
__global__ void k_bsum() {
    __shared__ int sh[256];
    int t = threadIdx.x, i = blockIdx.x * 256 + t;
    sh[t] = (i < NN) ? g_cnt[i] : 0;
    __syncthreads();
    for (int o = 128; o; o >>= 1) {
        if (t < o) sh[t] += sh[t + o];
        __syncthreads();
    }
    if (!t) g_bsum[blockIdx.x] = sh[0];
}
__global__ void k_bscan() {
    __shared__ int sh[256];
    int t = threadIdx.x;
    int v = (t < SBLK) ? g_bsum[t] : 0;
    sh[t] = v;
    __syncthreads();
    for (int o = 1; o < 256; o <<= 1) {
        int u = (t >= o) ? sh[t - o] : 0;
        __syncthreads();
        sh[t] += u;
        __syncthreads();
    }
    if (t < SBLK) g_boff[t] = sh[t] - v;
}
__global__ void k_wptr() {
    __shared__ int sh[256];
    int t = threadIdx.x, i = blockIdx.x * 256 + t;
    int v = (i < NN) ? g_cnt[i] : 0;
    sh[t] = v;
    __syncthreads();
    for (int o = 1; o < 256; o <<= 1) {
        int u = (t >= o) ? sh[t - o] : 0;
        __syncthreads();
        sh[t] += u;
        __syncthreads();
    }
    int excl = sh[t] - v + g_boff[blockIdx.x];
    if (i < NN) {
        g_rowptr[i] = excl;
        g_cursor[i] = excl;
        if (i == NN - 1) g_rowptr[NN] = excl + v;
    }
}
__global__ void k_scatter(const int* __restrict__ ei, const float* __restrict__ ew) {
    int e = blockIdx.x * blockDim.x + threadIdx.x;
    if (e < EE) {
        int s = ei[e];
        int d = ei[EE + e];
        int p = atomicAdd(&g_cursor[d], 1);
        float2 cv;
        cv.x = __int_as_float(s);
        cv.y = g_dis[s] * ew[e] * g_dis[d];
        g_cv[p] = cv;
    }
}

// ---------------- vectorized propagation kernels ----------------
template <bool PL>
__global__ void __launch_bounds__(256) k_prop2(const float* __restrict__ hin,
                                               float* __restrict__ hout,
                                               __nv_bfloat16* __restrict__ phi,
                                               __nv_bfloat16* __restrict__ plo) {
    int w = (blockIdx.x * 256 + threadIdx.x) >> 5;
    if (w >= NN) return;
    int lane = threadIdx.x & 31;
    int beg = g_rowptr[w], end = g_rowptr[w + 1];
    float2 acc = make_float2(0.f, 0.f);
    int p = beg;
    for (; p + 2 <= end; p += 2) {
        float2 cv0 = __ldg(&g_cv[p]);
        float2 cv1 = __ldg(&g_cv[p + 1]);
        float2 v0 = __ldg((const float2*)(hin + (size_t)__float_as_int(cv0.x) * 64) + lane);
        float2 v1 = __ldg((const float2*)(hin + (size_t)__float_as_int(cv1.x) * 64) + lane);
        acc.x += cv0.y * v0.x + cv1.y * v1.x;
        acc.y += cv0.y * v0.y + cv1.y * v1.y;
    }
    if (p < end) {
        float2 cv = __ldg(&g_cv[p]);
        float2 v = __ldg((const float2*)(hin + (size_t)__float_as_int(cv.x) * 64) + lane);
        acc.x += cv.y * v.x;
        acc.y += cv.y * v.y;
    }
    *((float2*)(hout + (size_t)w * 64) + lane) = acc;
    if (PL) {
        __nv_bfloat162 h2 = __floats2bfloat162_rn(acc.x, acc.y);
        float rx = acc.x - __bfloat162float(h2.x);
        float ry = acc.y - __bfloat162float(h2.y);
        *((__nv_bfloat162*)(phi + (size_t)w * 64) + lane) = h2;
        *((__nv_bfloat162*)(plo + (size_t)w * 64) + lane) = __floats2bfloat162_rn(rx, ry);
    }
}
template <bool PL>
__global__ void __launch_bounds__(256) k_prop4(const float* __restrict__ hin,
                                               float* __restrict__ hout,
                                               __nv_bfloat16* __restrict__ phi,
                                               __nv_bfloat16* __restrict__ plo) {
    int w = (blockIdx.x * 256 + threadIdx.x) >> 5;
    if (w >= NN) return;
    int lane = threadIdx.x & 31;
    int beg = g_rowptr[w], end = g_rowptr[w + 1];
    float4 acc = make_float4(0.f, 0.f, 0.f, 0.f);
    int p = beg;
    for (; p + 2 <= end; p += 2) {
        float2 cv0 = __ldg(&g_cv[p]);
        float2 cv1 = __ldg(&g_cv[p + 1]);
        float4 v0 = __ldg((const float4*)(hin + (size_t)__float_as_int(cv0.x) * 128) + lane);
        float4 v1 = __ldg((const float4*)(hin + (size_t)__float_as_int(cv1.x) * 128) + lane);
        acc.x += cv0.y * v0.x + cv1.y * v1.x;
        acc.y += cv0.y * v0.y + cv1.y * v1.y;
        acc.z += cv0.y * v0.z + cv1.y * v1.z;
        acc.w += cv0.y * v0.w + cv1.y * v1.w;
    }
    if (p < end) {
        float2 cv = __ldg(&g_cv[p]);
        float4 v = __ldg((const float4*)(hin + (size_t)__float_as_int(cv.x) * 128) + lane);
        acc.x += cv.y * v.x; acc.y += cv.y * v.y;
        acc.z += cv.y * v.z; acc.w += cv.y * v.w;
    }
    *((float4*)(hout + (size_t)w * 128) + lane) = acc;
    if (PL) {
        __nv_bfloat162 h0 = __floats2bfloat162_rn(acc.x, acc.y);
        __nv_bfloat162 h1 = __floats2bfloat162_rn(acc.z, acc.w);
        __nv_bfloat162 l0 = __floats2bfloat162_rn(acc.x - __bfloat162float(h0.x),
                                                  acc.y - __bfloat162float(h0.y));
        __nv_bfloat162 l1 = __floats2bfloat162_rn(acc.z - __bfloat162float(h1.x),
                                                  acc.w - __bfloat162float(h1.y));
        *((__nv_bfloat162*)(phi + (size_t)w * 128) + 2 * lane)     = h0;
        *((__nv_bfloat162*)(phi + (size_t)w * 128) + 2 * lane + 1) = h1;
        *((__nv_bfloat162*)(plo + (size_t)w * 128) + 2 * lane)     = l0;
        *((__nv_bfloat162*)(plo + (size_t)w * 128) + 2 * lane + 1) = l1;
    }
}
// CH=3 Horner step with fused add: hout = A*hin + Y; FIN: AC = relu(. + bias)
template <int FIN>
__global__ void __launch_bounds__(256) k_prop3add(const float* __restrict__ hin,
                                                  float* __restrict__ hout,
                                                  const float* __restrict__ Y,
                                                  const float* __restrict__ bias) {
    int w = (blockIdx.x * 256 + threadIdx.x) >> 5;
    if (w >= NN) return;
    int lane = threadIdx.x & 31;
    int beg = g_rowptr[w], end = g_rowptr[w + 1];
    float2 acc = make_float2(0.f, 0.f);
    float acc1 = 0.f;
    int p = beg;
    for (; p + 2 <= end; p += 2) {
        float2 cv0 = __ldg(&g_cv[p]);
        float2 cv1 = __ldg(&g_cv[p + 1]);
        const float* r0 = hin + (size_t)__float_as_int(cv0.x) * 96;
        const float* r1 = hin + (size_t)__float_as_int(cv1.x) * 96;
        float2 v0 = __ldg((const float2*)r0 + lane);
        float2 v1 = __ldg((const float2*)r1 + lane);
        float s0 = __ldg(r0 + 64 + lane);
        float s1 = __ldg(r1 + 64 + lane);
        acc.x += cv0.y * v0.x + cv1.y * v1.x;
        acc.y += cv0.y * v0.y + cv1.y * v1.y;
        acc1 += cv0.y * s0 + cv1.y * s1;
    }
    if (p < end) {
        float2 cv = __ldg(&g_cv[p]);
        const float* r = hin + (size_t)__float_as_int(cv.x) * 96;
        float2 v = __ldg((const float2*)r + lane);
        acc.x += cv.y * v.x;
        acc.y += cv.y * v.y;
        acc1 += cv.y * __ldg(r + 64 + lane);
    }
    float2 yv = __ldg((const float2*)(Y + (size_t)w * 96) + lane);
    float y1 = (64 + lane < 80) ? __ldg(Y + (size_t)w * 96 + 64 + lane) : 0.f;
    acc.x += yv.x;
    acc.y += yv.y;
    acc1 += y1;
    if (FIN) {
        acc.x = fmaxf(acc.x + bias[2 * lane], 0.f);
        acc.y = fmaxf(acc.y + bias[2 * lane + 1], 0.f);
        acc1 = (64 + lane < 80) ? fmaxf(acc1 + bias[64 + lane], 0.f) : 0.f;
    }
    *((float2*)(hout + (size_t)w * 96) + lane) = acc;
    hout[(size_t)w * 96 + 64 + lane] = acc1;
}

// ---------------- scalar propagation ----------------
template <bool ADD>
__global__ void __launch_bounds__(256) k_sprop(const float* __restrict__ hold,
                                               float* __restrict__ hnew,
                                               const float* __restrict__ addp) {
    int w = (blockIdx.x * 256 + threadIdx.x) >> 5;
    if (w >= NN) return;
    int lane = threadIdx.x & 31;
    int beg = g_rowptr[w], end = g_rowptr[w + 1];
    float s = 0.f;
    for (int p = beg + lane; p < end; p += 32) {
        float2 cv = __ldg(&g_cv[p]);
        s += cv.y * __ldg(&hold[__float_as_int(cv.x)]);
    }
#pragma unroll
    for (int o = 16; o; o >>= 1) s += __shfl_xor_sync(0xffffffffu, s, o);
    if (lane == 0) hnew[w] = ADD ? (s + addp[w]) : s;
}
__global__ void k_copy(const float* __restrict__ src, float* __restrict__ dst) {
    int i = blockIdx.x * blockDim.x + threadIdx.x;
    if (i < NN) dst[i] = src[i];
}

// ---------------- expand fp32 activations into bf16 hi/lo planes -------------
__global__ void k_expand(const float* __restrict__ src, int sX, int Kpad,
                         __nv_bfloat16* __restrict__ phi, __nv_bfloat16* __restrict__ plo) {
    int idx = blockIdx.x * 256 + threadIdx.x;
    if (idx >= NN * Kpad) return;
    int w = idx / Kpad, c = idx - w * Kpad;
    float v = src[(size_t)w * sX + c];
    __nv_bfloat16 h = __float2bfloat16(v);
    phi[idx] = h;
    plo[idx] = __float2bfloat16(v - __bfloat162float(h));
}

// ---------------- expand weights ----------------
__global__ void k_wexp(const float* __restrict__ W, int Cin, int Cout,
                       int Npad, int Kpad, __nv_bfloat16* __restrict__ dst) {
    int idx = blockIdx.x * 256 + threadIdx.x;
    int per = Npad * 2 * Kpad;
    if (idx >= 21 * per) return;
    int k = idx / per;
    int r = idx - k * per;
    int n = r / (2 * Kpad);
    int j = r - n * 2 * Kpad;
    int ki = (j >= Kpad) ? (j - Kpad) : j;
    float v = (n < Cout && ki < Cin)
                  ? __ldg(&W[(size_t)k * Cin * Cout + (size_t)ki * Cout + n]) : 0.f;
    dst[idx] = __float2bfloat16(v);
}

// ---------------- bf16 tensor GEMM ----------------
#define ASTR 40
template <int NT, int MODE, int NH>
__global__ void __launch_bounds__(256) k_gemm_bf(int Kpad, size_t abase, size_t slotOff,
                                                 const __nv_bfloat16* __restrict__ Wx,
                                                 int wRow, size_t wStep,
                                                 float* __restrict__ D, int sD, int Cout,
                                                 const float* __restrict__ bias,
                                                 float* __restrict__ D2, int sD2) {
    const int BN = 16 * NT;
    __shared__ __nv_bfloat16 As[128][ASTR];
    __shared__ __nv_bfloat16 Bs[BN][ASTR];
    int tid = threadIdx.x;
    int warp = tid >> 5, lane = tid & 31;
    int wm = warp >> 1, wn = warp & 1;
    int g = lane >> 2, q = lane & 3;
    int m0 = blockIdx.x * 128, n0 = blockIdx.y * BN;

    float acc[2][NT][4];
#pragma unroll
    for (int mt = 0; mt < 2; ++mt)
#pragma unroll
        for (int nt = 0; nt < NT; ++nt)
#pragma unroll
            for (int i = 0; i < 4; ++i) acc[mt][nt][i] = 0.f;

    int segch = Kpad >> 5;
    int nch = 2 * segch;

#pragma unroll
    for (int h = 0; h < NH; ++h) {
        const __nv_bfloat16* hip = g_Ahi + abase + (size_t)h * slotOff;
        const __nv_bfloat16* lop = g_Alo + abase + (size_t)h * slotOff;
        const __nv_bfloat16* Wh = Wx + (size_t)h * wStep;
        for (int c = 0; c < nch; ++c) {
            int seg = c / segch, cc = c - seg * segch;
            const __nv_bfloat16* ap = seg ? lop : hip;
#pragma unroll
            for (int i = tid; i < 512; i += 256) {
                int row = i >> 2, qq = i & 3;
                *(uint4*)&As[row][qq * 8] =
                    *(const uint4*)&ap[(size_t)(m0 + row) * Kpad + cc * 32 + qq * 8];
            }
            for (int i = tid; i < BN * 4; i += 256) {
                int row = i >> 2, qq = i & 3;
                *(uint4*)&Bs[row][qq * 8] =
                    *(const uint4*)&Wh[(size_t)(n0 + row) * wRow + c * 32 + qq * 8];
            }
            __syncthreads();
#pragma unroll
            for (int ks = 0; ks < 2; ++ks) {
                int kb = ks * 16;
                uint32_t a[2][4], b[NT][2];
#pragma unroll
                for (int mt = 0; mt < 2; ++mt) {
                    int mr = wm * 32 + mt * 16;
                    a[mt][0] = *(const uint32_t*)&As[mr + g][kb + 2 * q];
                    a[mt][1] = *(const uint32_t*)&As[mr + g + 8][kb + 2 * q];
                    a[mt][2] = *(const uint32_t*)&As[mr + g][kb + 2 * q + 8];
                    a[mt][3] = *(const uint32_t*)&As[mr + g + 8][kb + 2 * q + 8];
                }
#pragma unroll
                for (int nt = 0; nt < NT; ++nt) {
                    int nc = wn * (8 * NT) + nt * 8 + g;
                    b[nt][0] = *(const uint32_t*)&Bs[nc][kb + 2 * q];
                    b[nt][1] = *(const uint32_t*)&Bs[nc][kb + 2 * q + 8];
                }
#pragma unroll
                for (int mt = 0; mt < 2; ++mt)
#pragma unroll
                    for (int nt = 0; nt < NT; ++nt) mma_bf16(acc[mt][nt], a[mt], b[nt]);
            }
            __syncthreads();
        }
    }
#pragma unroll
    for (int mt = 0; mt < 2; ++mt) {
#pragma unroll
        for (int nt = 0; nt < NT; ++nt) {
#pragma unroll
            for (int i = 0; i < 4; ++i) {
                int gm = m0 + wm * 32 + mt * 16 + g + ((i >> 1) ? 8 : 0);
                int gn = n0 + wn * (8 * NT) + nt * 8 + q * 2 + (i & 1);
                if (gm >= NN || gn >= Cout) continue;
                float r = acc[mt][nt][i];
                if (MODE == 0) {
                    D[(size_t)gm * sD + gn] = r;
                } else if (MODE == 1) {
                    D[(size_t)gm * sD + gn] += r;
                } else {
                    float v = D[(size_t)gm * sD + gn] + r + bias[gn];
                    D2[(size_t)gm * sD2 + gn] = fmaxf(v, 0.f);
                }
            }
        }
    }
}

// ---------------- layer 1 head ----------------
__global__ void __launch_bounds__(256) k_head(const float* __restrict__ S,
                                              const float* __restrict__ W1,
                                              const float* __restrict__ b1) {
    int w = (blockIdx.x * 256 + threadIdx.x) >> 5;
    if (w >= NN) return;
    int lane = threadIdx.x & 31;
    float xk[21];
#pragma unroll
    for (int k = 0; k < 21; ++k) xk[k] = __ldg(&S[(size_t)k * RPAD + w]);
    for (int c = lane; c < 60; c += 32) {
        float a = b1[c];
#pragma unroll
        for (int k = 0; k < 21; ++k) a += xk[k] * __ldg(&W1[k * 60 + c]);
        g_XL[(size_t)w * 64 + c] = fmaxf(a, 0.f);
    }
}

// ---------------- layer 5 Y-stack ----------------
__global__ void __launch_bounds__(256) k_y5(const float* __restrict__ X,
                                            const float* __restrict__ W5,
                                            float* __restrict__ Y) {
    int w = (blockIdx.x * 256 + threadIdx.x) >> 5;
    if (w >= NN) return;
    int lane = threadIdx.x & 31;
    const float* xr = X + (size_t)w * 96;
    float x0 = xr[lane], x1 = xr[32 + lane];
    float x2 = (lane < 16) ? xr[64 + lane] : 0.f;
#pragma unroll
    for (int k = 0; k < 21; ++k) {
        float s = x0 * __ldg(&W5[k * 80 + lane]) + x1 * __ldg(&W5[k * 80 + 32 + lane]);
        if (lane < 16) s += x2 * __ldg(&W5[k * 80 + 64 + lane]);
#pragma unroll
        for (int o = 16; o; o >>= 1) s += __shfl_xor_sync(0xffffffffu, s, o);
        if (lane == 0) Y[(size_t)k * RPAD + w] = s;
    }
}

__global__ void k_sigmoid(const float* __restrict__ t, const float* __restrict__ b,
                          float* __restrict__ out) {
    int i = blockIdx.x * blockDim.x + threadIdx.x;
    if (i < NN) out[i] = 1.f / (1.f + expf(-(t[i] + b[0])));
}

// ---------------- host ----------------
extern "C" void kernel_launch(void* const* d_in, const int* in_sizes, int n_in,
                              void* d_out, int out_size) {
    const float* x  = (const float*)d_in[0];
    const int*   ei = (const int*)d_in[1];
    const float* ew = (const float*)d_in[2];
    const float* Wl[5]; const float* bl[5];
    for (int l = 0; l < 5; ++l) {
        Wl[l] = (const float*)d_in[3 + 2 * l];
        bl[l] = (const float*)d_in[4 + 2 * l];
    }
    float* out = (float*)d_out;

    float *XL, *A0, *A1, *AC;
    __nv_bfloat16 *Wexp, *Ahi, *Alo;
    cudaGetSymbolAddress((void**)&XL, g_XL);
    cudaGetSymbolAddress((void**)&A0, g_A0);
    cudaGetSymbolAddress((void**)&A1, g_A1);
    cudaGetSymbolAddress((void**)&AC, g_AC);
    cudaGetSymbolAddress((void**)&Wexp, g_Wexp);
    cudaGetSymbolAddress((void**)&Ahi, g_Ahi);
    cudaGetSymbolAddress((void**)&Alo, g_Alo);

    const int WG = (NN * 32 + 255) / 256;
    const int GM = RPAD / 128;

    const size_t H2 = 112 * 128;
    const size_t O2 = 0;
    const size_t H3 = 224 * 256;
    const size_t O3 = O2 + 21 * H2;
    const size_t H4 = 80 * 448;
    const size_t O4 = O3 + 21 * H3;

    cudaStream_t s2;
    cudaStreamCreateWithFlags(&s2, cudaStreamNonBlocking);
    cudaEvent_t ep[48], eg[48];
    for (int i = 0; i < 48; ++i) {
        cudaEventCreateWithFlags(&ep[i], cudaEventDisableTiming);
        cudaEventCreateWithFlags(&eg[i], cudaEventDisableTiming);
    }

    // ---- CSR build ----
    k_zero_nodes<<<(NN + 255) / 256, 256>>>();
    k_degcnt<<<(EE + 255) / 256, 256>>>(ei, ew);
    k_dis<<<(NN + 255) / 256, 256>>>();
    k_bsum<<<SBLK, 256>>>();
    k_bscan<<<1, 256>>>();
    k_wptr<<<SBLK, 256>>>();
    k_scatter<<<(EE + 255) / 256, 256>>>(ei, ew);

    // ---- weight expansions ----
    k_wexp<<<(int)((21 * H2 + 255) / 256), 256>>>(Wl[1], 60, 100, 112, 64, Wexp + O2);
    k_wexp<<<(int)((21 * H3 + 255) / 256), 256>>>(Wl[2], 100, 200, 224, 128, Wexp + O3);
    k_wexp<<<(int)((21 * H4 + 255) / 256), 256>>>(Wl[3], 200, 80, 80, 224, Wexp + O4);

    // ---- layer 1: scalar hop stack in A0, fused head GEMV ----
    k_copy<<<(NN + 255) / 256, 256>>>(x, A0);
    for (int k = 1; k <= KH; ++k)
        k_sprop<false><<<WG, 256>>>(A0 + (size_t)(k - 1) * RPAD, A0 + (size_t)k * RPAD, 0);
    k_head<<<WG, 256>>>(A0, Wl[0], bl[0]);

    // ---- layer 2: overlapped hop-paired ----
    {
        const size_t SL = (size_t)RPAD * 64;
        dim3 g(GM, 1);
        k_expand<<<(NN * 64 + 255) / 256, 256>>>(XL, 64, 64, Ahi, Alo);
        k_prop2<true><<<WG, 256>>>(XL, A0, Ahi + SL, Alo + SL);
        cudaEventRecord(ep[0], 0);
        cudaStreamWaitEvent(s2, ep[0], 0);
        k_gemm_bf<7, 0, 2><<<g, 256, 0, s2>>>(64, 0, SL, Wexp + O2, 128, H2,
                                              AC, 128, 100, 0, 0, 0);
        cudaEventRecord(eg[0], s2);
        for (int j = 1; j <= 9; ++j) {
            size_t base = (j & 1) ? 2 * SL : 0;
            if (j >= 2) cudaStreamWaitEvent(0, eg[j - 2], 0);
            k_prop2<true><<<WG, 256>>>(A0, A1, Ahi + base, Alo + base);
            k_prop2<true><<<WG, 256>>>(A1, A0, Ahi + base + SL, Alo + base + SL);
            cudaEventRecord(ep[j], 0);
            cudaStreamWaitEvent(s2, ep[j], 0);
            k_gemm_bf<7, 1, 2><<<g, 256, 0, s2>>>(64, base, SL,
                                                  Wexp + O2 + (size_t)(2 * j) * H2, 128, H2,
                                                  AC, 128, 100, 0, 0, 0);
            cudaEventRecord(eg[j], s2);
        }
        cudaStreamWaitEvent(0, eg[8], 0);
        k_prop2<true><<<WG, 256>>>(A0, A1, Ahi, Alo);
        cudaEventRecord(ep[10], 0);
        cudaStreamWaitEvent(s2, ep[10], 0);
        k_gemm_bf<7, 2, 1><<<g, 256, 0, s2>>>(64, 0, 0, Wexp + O2 + (size_t)KH * H2, 128, 0,
                                              AC, 128, 100, bl[1], XL, 128);
        cudaEventRecord(eg[10], s2);
        cudaStreamWaitEvent(0, eg[10], 0);
    }

    // ---- layer 3: overlapped hop-paired ----
    {
        const size_t SL = (size_t)RPAD * 128;
        dim3 g(GM, 2);
        k_expand<<<(NN * 128 + 255) / 256, 256>>>(XL, 128, 128, Ahi, Alo);
        k_prop4<true><<<WG, 256>>>(XL, A0, Ahi + SL, Alo + SL);
        cudaEventRecord(ep[11], 0);
        cudaStreamWaitEvent(s2, ep[11], 0);
        k_gemm_bf<7, 0, 2><<<g, 256, 0, s2>>>(128, 0, SL, Wexp + O3, 256, H3,
                                              AC, 224, 200, 0, 0, 0);
        cudaEventRecord(eg[11], s2);
        for (int j = 1; j <= 9; ++j) {
            size_t base = (j & 1) ? 2 * SL : 0;
            if (j >= 2) cudaStreamWaitEvent(0, eg[11 + j - 2], 0);
            k_prop4<true><<<WG, 256>>>(A0, A1, Ahi + base, Alo + base);
            k_prop4<true><<<WG, 256>>>(A1, A0, Ahi + base + SL, Alo + base + SL);
            cudaEventRecord(ep[11 + j], 0);
            cudaStreamWaitEvent(s2, ep[11 + j], 0);
            k_gemm_bf<7, 1, 2><<<g, 256, 0, s2>>>(128, base, SL,
                                                  Wexp + O3 + (size_t)(2 * j) * H3, 256, H3,
                                                  AC, 224, 200, 0, 0, 0);
            cudaEventRecord(eg[11 + j], s2);
        }
        cudaStreamWaitEvent(0, eg[11 + 8], 0);
        k_prop4<true><<<WG, 256>>>(A0, A1, Ahi, Alo);
        cudaEventRecord(ep[21], 0);
        cudaStreamWaitEvent(s2, ep[21], 0);
        k_gemm_bf<7, 2, 1><<<g, 256, 0, s2>>>(128, 0, 0, Wexp + O3 + (size_t)KH * H3, 256, 0,
                                              AC, 224, 200, bl[2], XL, 224);
        cudaEventRecord(eg[21], s2);
        cudaStreamWaitEvent(0, eg[21], 0);
    }

    // ---- layer 4: pipelined Horner (GEMMs on s2, fused prop+add on s0) ----
    {
        dim3 g(GM, 1);
        float* Yb[2] = {XL, XL + (size_t)RPAD * 96};   // XL reused as Y double-buffer
        k_expand<<<(NN * 224 + 255) / 256, 256>>>(XL, 224, 224, Ahi, Alo);
        cudaEventRecord(ep[44], 0);
        cudaStreamWaitEvent(s2, ep[44], 0);
        // initial t = Y_KH -> A0 (on s2)
        k_gemm_bf<5, 0, 1><<<g, 256, 0, s2>>>(224, 0, 0, Wexp + O4 + (size_t)KH * H4, 448, 0,
                                              A0, 96, 80, 0, 0, 0);
        cudaEventRecord(eg[43], s2);
        // prefill Y_{KH-1}, Y_{KH-2}
        k_gemm_bf<5, 0, 1><<<g, 256, 0, s2>>>(224, 0, 0, Wexp + O4 + (size_t)(KH - 1) * H4,
                                              448, 0, Yb[(KH - 1) & 1], 96, 80, 0, 0, 0);
        cudaEventRecord(eg[22 + KH - 1], s2);
        k_gemm_bf<5, 0, 1><<<g, 256, 0, s2>>>(224, 0, 0, Wexp + O4 + (size_t)(KH - 2) * H4,
                                              448, 0, Yb[(KH - 2) & 1], 96, 80, 0, 0, 0);
        cudaEventRecord(eg[22 + KH - 2], s2);
        cudaStreamWaitEvent(0, eg[43], 0);

        float* t = A0;
        float* o = A1;
        for (int k = KH - 1; k >= 1; --k) {
            cudaStreamWaitEvent(0, eg[22 + k], 0);
            k_prop3add<0><<<WG, 256>>>(t, o, Yb[k & 1], 0);
            cudaEventRecord(ep[22 + k], 0);
            if (k - 2 >= 0) {   // refill the parity slot just freed
                cudaStreamWaitEvent(s2, ep[22 + k], 0);
                k_gemm_bf<5, 0, 1><<<g, 256, 0, s2>>>(224, 0, 0,
                                                      Wexp + O4 + (size_t)(k - 2) * H4,
                                                      448, 0, Yb[(k - 2) & 1], 96, 80, 0, 0, 0);
                cudaEventRecord(eg[22 + k - 2], s2);
            }
            float* tmp = t; t = o; o = tmp;
        }
        cudaStreamWaitEvent(0, eg[22], 0);
        k_prop3add<1><<<WG, 256>>>(t, AC, Yb[0], bl[3]);
    }

    // ---- layer 5: Y-stack in XL, scalar Horner ----
    k_y5<<<WG, 256>>>(AC, Wl[4], XL);
    {
        const float* hold = XL + (size_t)KH * RPAD;
        float* cur = A0;
        float* nxt = A1;
        for (int k = KH - 1; k >= 0; --k) {
            k_sprop<true><<<WG, 256>>>(hold, cur, XL + (size_t)k * RPAD);
            hold = cur;
            float* tmp = cur; cur = nxt; nxt = tmp;
        }
        k_sigmoid<<<(NN + 255) / 256, 256>>>(hold, bl[4], out);
    }
}

// round 16
// speedup vs baseline: 1.6720x; 1.0401x over previous
#include <cuda_runtime.h>
#include <cuda_bf16.h>
#include <cstdint>
#include <math.h>

#define NN 50000
#define RPAD 50176
#define EE 800000
#define KH 20
#define SBLK 196

// ---------------- scratch ----------------
__device__ float g_XL[(size_t)RPAD * 224];
__device__ float g_A0[(size_t)RPAD * 224];
__device__ float g_A1[(size_t)RPAD * 224];
__device__ float g_AC[(size_t)RPAD * 224];
__device__ __nv_bfloat16 g_Ahi[(size_t)RPAD * 512];   // 4 plane slots
__device__ __nv_bfloat16 g_Alo[(size_t)RPAD * 512];
__device__ __nv_bfloat16 g_Wexp[4644864];
__device__ float  g_deg[NN];
__device__ float  g_dis[NN];
__device__ int    g_cnt[NN];
__device__ int    g_rowptr[NN + 1];
__device__ int    g_cursor[NN];
__device__ int    g_bsum[256];
__device__ int    g_boff[256];
__device__ float2 g_cv[EE];

// ---------------- bf16 mma helper ----------------
__device__ __forceinline__ void mma_bf16(float* c, const uint32_t* a, const uint32_t* b) {
    asm volatile(
        "mma.sync.aligned.m16n8k16.row.col.f32.bf16.bf16.f32 "
        "{%0,%1,%2,%3}, {%4,%5,%6,%7}, {%8,%9}, {%0,%1,%2,%3};"
        : "+f"(c[0]), "+f"(c[1]), "+f"(c[2]), "+f"(c[3])
        : "r"(a[0]), "r"(a[1]), "r"(a[2]), "r"(a[3]), "r"(b[0]), "r"(b[1]));
}

// ---------------- CSR build ----------------
__global__ void k_zero_nodes() {
    int i = blockIdx.x * blockDim.x + threadIdx.x;
    if (i < NN) { g_deg[i] = 0.f; g_cnt[i] = 0; }
}
__global__ void k_degcnt(const int* __restrict__ ei, const float* __restrict__ ew) {
    int e = blockIdx.x * blockDim.x + threadIdx.x;
    if (e < EE) {
        int d = ei[EE + e];
        atomicAdd(&g_deg[d], ew[e]);
        atomicAdd(&g_cnt[d], 1);
    }
}
__global__ void k_dis() {
    int i = blockIdx.x * blockDim.x + threadIdx.x;
    if (i < NN) {
        float d = g_deg[i];
        g_dis[i] = (d > 0.f) ? rsqrtf(d) : 0.f;
    }
}
__global__ void k_bsum() {
    __shared__ int sh[256];
    int t = threadIdx.x, i = blockIdx.x * 256 + t;
    sh[t] = (i < NN) ? g_cnt[i] : 0;
    __syncthreads();
    for (int o = 128; o; o >>= 1) {
        if (t < o) sh[t] += sh[t + o];
        __syncthreads();
    }
    if (!t) g_bsum[blockIdx.x] = sh[0];
}
__global__ void k_bscan() {
    __shared__ int sh[256];
    int t = threadIdx.x;
    int v = (t < SBLK) ? g_bsum[t] : 0;
    sh[t] = v;
    __syncthreads();
    for (int o = 1; o < 256; o <<= 1) {
        int u = (t >= o) ? sh[t - o] : 0;
        __syncthreads();
        sh[t] += u;
        __syncthreads();
    }
    if (t < SBLK) g_boff[t] = sh[t] - v;
}
__global__ void k_wptr() {
    __shared__ int sh[256];
    int t = threadIdx.x, i = blockIdx.x * 256 + t;
    int v = (i < NN) ? g_cnt[i] : 0;
    sh[t] = v;
    __syncthreads();
    for (int o = 1; o < 256; o <<= 1) {
        int u = (t >= o) ? sh[t - o] : 0;
        __syncthreads();
        sh[t] += u;
        __syncthreads();
    }
    int excl = sh[t] - v + g_boff[blockIdx.x];
    if (i < NN) {
        g_rowptr[i] = excl;
        g_cursor[i] = excl;
        if (i == NN - 1) g_rowptr[NN] = excl + v;
    }
}
__global__ void k_scatter(const int* __restrict__ ei, const float* __restrict__ ew) {
    int e = blockIdx.x * blockDim.x + threadIdx.x;
    if (e < EE) {
        int s = ei[e];
        int d = ei[EE + e];
        int p = atomicAdd(&g_cursor[d], 1);
        float2 cv;
        cv.x = __int_as_float(s);
        cv.y = g_dis[s] * ew[e] * g_dis[d];
        g_cv[p] = cv;
    }
}

// ---------------- prop CH=2 (stride 64) + planes ----------------
template <bool PL>
__global__ void __launch_bounds__(256) k_prop2(const float* __restrict__ hin,
                                               float* __restrict__ hout,
                                               __nv_bfloat16* __restrict__ phi,
                                               __nv_bfloat16* __restrict__ plo) {
    int w = (blockIdx.x * 256 + threadIdx.x) >> 5;
    if (w >= NN) return;
    int lane = threadIdx.x & 31;
    int beg = g_rowptr[w], end = g_rowptr[w + 1];
    float2 acc = make_float2(0.f, 0.f);
    int p = beg;
    for (; p + 2 <= end; p += 2) {
        float2 cv0 = __ldg(&g_cv[p]);
        float2 cv1 = __ldg(&g_cv[p + 1]);
        float2 v0 = __ldg((const float2*)(hin + (size_t)__float_as_int(cv0.x) * 64) + lane);
        float2 v1 = __ldg((const float2*)(hin + (size_t)__float_as_int(cv1.x) * 64) + lane);
        acc.x += cv0.y * v0.x + cv1.y * v1.x;
        acc.y += cv0.y * v0.y + cv1.y * v1.y;
    }
    if (p < end) {
        float2 cv = __ldg(&g_cv[p]);
        float2 v = __ldg((const float2*)(hin + (size_t)__float_as_int(cv.x) * 64) + lane);
        acc.x += cv.y * v.x;
        acc.y += cv.y * v.y;
    }
    *((float2*)(hout + (size_t)w * 64) + lane) = acc;
    if (PL) {
        __nv_bfloat162 h2 = __floats2bfloat162_rn(acc.x, acc.y);
        float rx = acc.x - __bfloat162float(h2.x);
        float ry = acc.y - __bfloat162float(h2.y);
        *((__nv_bfloat162*)(phi + (size_t)w * 64) + lane) = h2;
        *((__nv_bfloat162*)(plo + (size_t)w * 64) + lane) = __floats2bfloat162_rn(rx, ry);
    }
}

// ---------------- prop L3 (stride 104, planes at Kpad=128) ----------------
__global__ void __launch_bounds__(256) k_prop4p(const float* __restrict__ hin,
                                                float* __restrict__ hout,
                                                __nv_bfloat16* __restrict__ phi,
                                                __nv_bfloat16* __restrict__ plo) {
    int w = (blockIdx.x * 256 + threadIdx.x) >> 5;
    if (w >= NN) return;
    int lane = threadIdx.x & 31;
    if (lane >= 26) return;               // 26 lanes x float4 = 104 channels
    int beg = g_rowptr[w], end = g_rowptr[w + 1];
    float4 acc = make_float4(0.f, 0.f, 0.f, 0.f);
    int p = beg;
    for (; p + 2 <= end; p += 2) {
        float2 cv0 = __ldg(&g_cv[p]);
        float2 cv1 = __ldg(&g_cv[p + 1]);
        float4 v0 = __ldg((const float4*)(hin + (size_t)__float_as_int(cv0.x) * 104) + lane);
        float4 v1 = __ldg((const float4*)(hin + (size_t)__float_as_int(cv1.x) * 104) + lane);
        acc.x += cv0.y * v0.x + cv1.y * v1.x;
        acc.y += cv0.y * v0.y + cv1.y * v1.y;
        acc.z += cv0.y * v0.z + cv1.y * v1.z;
        acc.w += cv0.y * v0.w + cv1.y * v1.w;
    }
    if (p < end) {
        float2 cv = __ldg(&g_cv[p]);
        float4 v = __ldg((const float4*)(hin + (size_t)__float_as_int(cv.x) * 104) + lane);
        acc.x += cv.y * v.x; acc.y += cv.y * v.y;
        acc.z += cv.y * v.z; acc.w += cv.y * v.w;
    }
    *((float4*)(hout + (size_t)w * 104) + lane) = acc;
    __nv_bfloat162 h0 = __floats2bfloat162_rn(acc.x, acc.y);
    __nv_bfloat162 h1 = __floats2bfloat162_rn(acc.z, acc.w);
    __nv_bfloat162 l0 = __floats2bfloat162_rn(acc.x - __bfloat162float(h0.x),
                                              acc.y - __bfloat162float(h0.y));
    __nv_bfloat162 l1 = __floats2bfloat162_rn(acc.z - __bfloat162float(h1.x),
                                              acc.w - __bfloat162float(h1.y));
    *((__nv_bfloat162*)(phi + (size_t)w * 128) + 2 * lane)     = h0;
    *((__nv_bfloat162*)(phi + (size_t)w * 128) + 2 * lane + 1) = h1;
    *((__nv_bfloat162*)(plo + (size_t)w * 128) + 2 * lane)     = l0;
    *((__nv_bfloat162*)(plo + (size_t)w * 128) + 2 * lane + 1) = l1;
}

// ---------------- L4 Horner step (stride 80): hout = A*hin + Y ---------------
// FIN: hout = relu(. + bias)
template <int FIN>
__global__ void __launch_bounds__(256) k_prop3add(const float* __restrict__ hin,
                                                  float* __restrict__ hout,
                                                  const float* __restrict__ Y,
                                                  const float* __restrict__ bias) {
    int w = (blockIdx.x * 256 + threadIdx.x) >> 5;
    if (w >= NN) return;
    int lane = threadIdx.x & 31;
    int beg = g_rowptr[w], end = g_rowptr[w + 1];
    float2 acc = make_float2(0.f, 0.f);
    float acc1 = 0.f;
    int p = beg;
    for (; p + 2 <= end; p += 2) {
        float2 cv0 = __ldg(&g_cv[p]);
        float2 cv1 = __ldg(&g_cv[p + 1]);
        const float* r0 = hin + (size_t)__float_as_int(cv0.x) * 80;
        const float* r1 = hin + (size_t)__float_as_int(cv1.x) * 80;
        float2 v0 = __ldg((const float2*)r0 + lane);
        float2 v1 = __ldg((const float2*)r1 + lane);
        acc.x += cv0.y * v0.x + cv1.y * v1.x;
        acc.y += cv0.y * v0.y + cv1.y * v1.y;
        if (lane < 16) acc1 += cv0.y * __ldg(r0 + 64 + lane) + cv1.y * __ldg(r1 + 64 + lane);
    }
    if (p < end) {
        float2 cv = __ldg(&g_cv[p]);
        const float* r = hin + (size_t)__float_as_int(cv.x) * 80;
        float2 v = __ldg((const float2*)r + lane);
        acc.x += cv.y * v.x;
        acc.y += cv.y * v.y;
        if (lane < 16) acc1 += cv.y * __ldg(r + 64 + lane);
    }
    float2 yv = __ldg((const float2*)(Y + (size_t)w * 80) + lane);
    acc.x += yv.x;
    acc.y += yv.y;
    if (lane < 16) acc1 += __ldg(Y + (size_t)w * 80 + 64 + lane);
    if (FIN) {
        acc.x = fmaxf(acc.x + bias[2 * lane], 0.f);
        acc.y = fmaxf(acc.y + bias[2 * lane + 1], 0.f);
        if (lane < 16) acc1 = fmaxf(acc1 + bias[64 + lane], 0.f);
    }
    *((float2*)(hout + (size_t)w * 80) + lane) = acc;
    if (lane < 16) hout[(size_t)w * 80 + 64 + lane] = acc1;
}

// ---------------- scalar propagation ----------------
// MODE 0: hnew = A*hold   MODE 1: hnew = A*hold + addp
// MODE 2: hnew = sigmoid(A*hold + addp + bias[0])
template <int MODE>
__global__ void __launch_bounds__(256) k_sprop(const float* __restrict__ hold,
                                               float* __restrict__ hnew,
                                               const float* __restrict__ addp,
                                               const float* __restrict__ bias) {
    int w = (blockIdx.x * 256 + threadIdx.x) >> 5;
    if (w >= NN) return;
    int lane = threadIdx.x & 31;
    int beg = g_rowptr[w], end = g_rowptr[w + 1];
    float s = 0.f;
    for (int p = beg + lane; p < end; p += 32) {
        float2 cv = __ldg(&g_cv[p]);
        s += cv.y * __ldg(&hold[__float_as_int(cv.x)]);
    }
#pragma unroll
    for (int o = 16; o; o >>= 1) s += __shfl_xor_sync(0xffffffffu, s, o);
    if (lane == 0) {
        if (MODE == 0) hnew[w] = s;
        else if (MODE == 1) hnew[w] = s + addp[w];
        else hnew[w] = 1.f / (1.f + expf(-(s + addp[w] + bias[0])));
    }
}
__global__ void k_copy(const float* __restrict__ src, float* __restrict__ dst) {
    int i = blockIdx.x * blockDim.x + threadIdx.x;
    if (i < NN) dst[i] = src[i];
}

// ---------------- expand fp32 -> bf16 hi/lo planes ----------------
__global__ void k_expand(const float* __restrict__ src, int sX, int Kpad, int realK,
                         __nv_bfloat16* __restrict__ phi, __nv_bfloat16* __restrict__ plo) {
    int idx = blockIdx.x * 256 + threadIdx.x;
    if (idx >= NN * Kpad) return;
    int w = idx / Kpad, c = idx - w * Kpad;
    float v = (c < realK) ? src[(size_t)w * sX + c] : 0.f;
    __nv_bfloat16 h = __float2bfloat16(v);
    phi[idx] = h;
    plo[idx] = __float2bfloat16(v - __bfloat162float(h));
}

// ---------------- expand weights ----------------
__global__ void k_wexp(const float* __restrict__ W, int Cin, int Cout,
                       int Npad, int Kpad, __nv_bfloat16* __restrict__ dst) {
    int idx = blockIdx.x * 256 + threadIdx.x;
    int per = Npad * 2 * Kpad;
    if (idx >= 21 * per) return;
    int k = idx / per;
    int r = idx - k * per;
    int n = r / (2 * Kpad);
    int j = r - n * 2 * Kpad;
    int ki = (j >= Kpad) ? (j - Kpad) : j;
    float v = (n < Cout && ki < Cin)
                  ? __ldg(&W[(size_t)k * Cin * Cout + (size_t)ki * Cout + n]) : 0.f;
    dst[idx] = __float2bfloat16(v);
}

// ---------------- bf16 tensor GEMM ----------------
#define ASTR 40
template <int NT, int MODE, int NH>
__global__ void __launch_bounds__(256) k_gemm_bf(int Kpad, size_t abase, size_t slotOff,
                                                 const __nv_bfloat16* __restrict__ Wx,
                                                 int wRow, size_t wStep,
                                                 float* __restrict__ D, int sD, int Cout,
                                                 const float* __restrict__ bias,
                                                 float* __restrict__ D2, int sD2) {
    const int BN = 16 * NT;
    __shared__ __nv_bfloat16 As[128][ASTR];
    __shared__ __nv_bfloat16 Bs[BN][ASTR];
    int tid = threadIdx.x;
    int warp = tid >> 5, lane = tid & 31;
    int wm = warp >> 1, wn = warp & 1;
    int g = lane >> 2, q = lane & 3;
    int m0 = blockIdx.x * 128, n0 = blockIdx.y * BN;

    float acc[2][NT][4];
#pragma unroll
    for (int mt = 0; mt < 2; ++mt)
#pragma unroll
        for (int nt = 0; nt < NT; ++nt)
#pragma unroll
            for (int i = 0; i < 4; ++i) acc[mt][nt][i] = 0.f;

    int segch = Kpad >> 5;
    int nch = 2 * segch;

#pragma unroll
    for (int h = 0; h < NH; ++h) {
        const __nv_bfloat16* hip = g_Ahi + abase + (size_t)h * slotOff;
        const __nv_bfloat16* lop = g_Alo + abase + (size_t)h * slotOff;
        const __nv_bfloat16* Wh = Wx + (size_t)h * wStep;
        for (int c = 0; c < nch; ++c) {
            int seg = c / segch, cc = c - seg * segch;
            const __nv_bfloat16* ap = seg ? lop : hip;
#pragma unroll
            for (int i = tid; i < 512; i += 256) {
                int row = i >> 2, qq = i & 3;
                *(uint4*)&As[row][qq * 8] =
                    *(const uint4*)&ap[(size_t)(m0 + row) * Kpad + cc * 32 + qq * 8];
            }
            for (int i = tid; i < BN * 4; i += 256) {
                int row = i >> 2, qq = i & 3;
                *(uint4*)&Bs[row][qq * 8] =
                    *(const uint4*)&Wh[(size_t)(n0 + row) * wRow + c * 32 + qq * 8];
            }
            __syncthreads();
#pragma unroll
            for (int ks = 0; ks < 2; ++ks) {
                int kb = ks * 16;
                uint32_t a[2][4], b[NT][2];
#pragma unroll
                for (int mt = 0; mt < 2; ++mt) {
                    int mr = wm * 32 + mt * 16;
                    a[mt][0] = *(const uint32_t*)&As[mr + g][kb + 2 * q];
                    a[mt][1] = *(const uint32_t*)&As[mr + g + 8][kb + 2 * q];
                    a[mt][2] = *(const uint32_t*)&As[mr + g][kb + 2 * q + 8];
                    a[mt][3] = *(const uint32_t*)&As[mr + g + 8][kb + 2 * q + 8];
                }
#pragma unroll
                for (int nt = 0; nt < NT; ++nt) {
                    int nc = wn * (8 * NT) + nt * 8 + g;
                    b[nt][0] = *(const uint32_t*)&Bs[nc][kb + 2 * q];
                    b[nt][1] = *(const uint32_t*)&Bs[nc][kb + 2 * q + 8];
                }
#pragma unroll
                for (int mt = 0; mt < 2; ++mt)
#pragma unroll
                    for (int nt = 0; nt < NT; ++nt) mma_bf16(acc[mt][nt], a[mt], b[nt]);
            }
            __syncthreads();
        }
    }
#pragma unroll
    for (int mt = 0; mt < 2; ++mt) {
#pragma unroll
        for (int nt = 0; nt < NT; ++nt) {
#pragma unroll
            for (int i = 0; i < 4; ++i) {
                int gm = m0 + wm * 32 + mt * 16 + g + ((i >> 1) ? 8 : 0);
                int gn = n0 + wn * (8 * NT) + nt * 8 + q * 2 + (i & 1);
                if (gm >= NN || gn >= Cout) continue;
                float r = acc[mt][nt][i];
                if (MODE == 0) {
                    D[(size_t)gm * sD + gn] = r;
                } else if (MODE == 1) {
                    D[(size_t)gm * sD + gn] += r;
                } else {
                    float v = D[(size_t)gm * sD + gn] + r + bias[gn];
                    D2[(size_t)gm * sD2 + gn] = fmaxf(v, 0.f);
                }
            }
        }
    }
}

// ---------------- layer 1 head ----------------
__global__ void __launch_bounds__(256) k_head(const float* __restrict__ S,
                                              const float* __restrict__ W1,
                                              const float* __restrict__ b1) {
    int w = (blockIdx.x * 256 + threadIdx.x) >> 5;
    if (w >= NN) return;
    int lane = threadIdx.x & 31;
    float xk[21];
#pragma unroll
    for (int k = 0; k < 21; ++k) xk[k] = __ldg(&S[(size_t)k * RPAD + w]);
    for (int c = lane; c < 60; c += 32) {
        float a = b1[c];
#pragma unroll
        for (int k = 0; k < 21; ++k) a += xk[k] * __ldg(&W1[k * 60 + c]);
        g_XL[(size_t)w * 64 + c] = fmaxf(a, 0.f);
    }
}

// ---------------- layer 5 Y-stack (X stride 80) ----------------
__global__ void __launch_bounds__(256) k_y5(const float* __restrict__ X,
                                            const float* __restrict__ W5,
                                            float* __restrict__ Y) {
    int w = (blockIdx.x * 256 + threadIdx.x) >> 5;
    if (w >= NN) return;
    int lane = threadIdx.x & 31;
    const float* xr = X + (size_t)w * 80;
    float x0 = xr[lane], x1 = xr[32 + lane];
    float x2 = (lane < 16) ? xr[64 + lane] : 0.f;
#pragma unroll
    for (int k = 0; k < 21; ++k) {
        float s = x0 * __ldg(&W5[k * 80 + lane]) + x1 * __ldg(&W5[k * 80 + 32 + lane]);
        if (lane < 16) s += x2 * __ldg(&W5[k * 80 + 64 + lane]);
#pragma unroll
        for (int o = 16; o; o >>= 1) s += __shfl_xor_sync(0xffffffffu, s, o);
        if (lane == 0) Y[(size_t)k * RPAD + w] = s;
    }
}

// ---------------- host ----------------
extern "C" void kernel_launch(void* const* d_in, const int* in_sizes, int n_in,
                              void* d_out, int out_size) {
    const float* x  = (const float*)d_in[0];
    const int*   ei = (const int*)d_in[1];
    const float* ew = (const float*)d_in[2];
    const float* Wl[5]; const float* bl[5];
    for (int l = 0; l < 5; ++l) {
        Wl[l] = (const float*)d_in[3 + 2 * l];
        bl[l] = (const float*)d_in[4 + 2 * l];
    }
    float* out = (float*)d_out;

    float *XL, *A0, *A1, *AC;
    __nv_bfloat16 *Wexp, *Ahi, *Alo;
    cudaGetSymbolAddress((void**)&XL, g_XL);
    cudaGetSymbolAddress((void**)&A0, g_A0);
    cudaGetSymbolAddress((void**)&A1, g_A1);
    cudaGetSymbolAddress((void**)&AC, g_AC);
    cudaGetSymbolAddress((void**)&Wexp, g_Wexp);
    cudaGetSymbolAddress((void**)&Ahi, g_Ahi);
    cudaGetSymbolAddress((void**)&Alo, g_Alo);

    const int WG = (NN * 32 + 255) / 256;
    const int GM = RPAD / 128;

    const size_t H2 = 112 * 128;
    const size_t O2 = 0;
    const size_t H3 = 224 * 256;
    const size_t O3 = O2 + 21 * H2;
    const size_t H4 = 80 * 448;
    const size_t O4 = O3 + 21 * H3;

    cudaStream_t s2;
    cudaStreamCreateWithFlags(&s2, cudaStreamNonBlocking);
    cudaEvent_t ep[48], eg[48];
    for (int i = 0; i < 48; ++i) {
        cudaEventCreateWithFlags(&ep[i], cudaEventDisableTiming);
        cudaEventCreateWithFlags(&eg[i], cudaEventDisableTiming);
    }

    // ---- weight expansions on s2 (overlap CSR build + L1 on s0) ----
    k_wexp<<<(int)((21 * H2 + 255) / 256), 256, 0, s2>>>(Wl[1], 60, 100, 112, 64, Wexp + O2);
    k_wexp<<<(int)((21 * H3 + 255) / 256), 256, 0, s2>>>(Wl[2], 100, 200, 224, 128, Wexp + O3);
    k_wexp<<<(int)((21 * H4 + 255) / 256), 256, 0, s2>>>(Wl[3], 200, 80, 80, 224, Wexp + O4);

    // ---- CSR build ----
    k_zero_nodes<<<(NN + 255) / 256, 256>>>();
    k_degcnt<<<(EE + 255) / 256, 256>>>(ei, ew);
    k_dis<<<(NN + 255) / 256, 256>>>();
    k_bsum<<<SBLK, 256>>>();
    k_bscan<<<1, 256>>>();
    k_wptr<<<SBLK, 256>>>();
    k_scatter<<<(EE + 255) / 256, 256>>>(ei, ew);

    // ---- layer 1: scalar hop stack in A0, fused head GEMV ----
    k_copy<<<(NN + 255) / 256, 256>>>(x, A0);
    for (int k = 1; k <= KH; ++k)
        k_sprop<0><<<WG, 256>>>(A0 + (size_t)(k - 1) * RPAD, A0 + (size_t)k * RPAD, 0, 0);
    k_head<<<WG, 256>>>(A0, Wl[0], bl[0]);

    // ---- layer 2: overlapped hop-paired; final writes XL stride 104 ----
    {
        const size_t SL = (size_t)RPAD * 64;
        dim3 g(GM, 1);
        k_expand<<<(NN * 64 + 255) / 256, 256>>>(XL, 64, 64, 64, Ahi, Alo);
        k_prop2<true><<<WG, 256>>>(XL, A0, Ahi + SL, Alo + SL);
        cudaEventRecord(ep[0], 0);
        cudaStreamWaitEvent(s2, ep[0], 0);
        k_gemm_bf<7, 0, 2><<<g, 256, 0, s2>>>(64, 0, SL, Wexp + O2, 128, H2,
                                              AC, 128, 100, 0, 0, 0);
        cudaEventRecord(eg[0], s2);
        for (int j = 1; j <= 9; ++j) {
            size_t base = (j & 1) ? 2 * SL : 0;
            if (j >= 2) cudaStreamWaitEvent(0, eg[j - 2], 0);
            k_prop2<true><<<WG, 256>>>(A0, A1, Ahi + base, Alo + base);
            k_prop2<true><<<WG, 256>>>(A1, A0, Ahi + base + SL, Alo + base + SL);
            cudaEventRecord(ep[j], 0);
            cudaStreamWaitEvent(s2, ep[j], 0);
            k_gemm_bf<7, 1, 2><<<g, 256, 0, s2>>>(64, base, SL,
                                                  Wexp + O2 + (size_t)(2 * j) * H2, 128, H2,
                                                  AC, 128, 100, 0, 0, 0);
            cudaEventRecord(eg[j], s2);
        }
        cudaStreamWaitEvent(0, eg[8], 0);
        k_prop2<true><<<WG, 256>>>(A0, A1, Ahi, Alo);
        cudaEventRecord(ep[10], 0);
        cudaStreamWaitEvent(s2, ep[10], 0);
        k_gemm_bf<7, 2, 1><<<g, 256, 0, s2>>>(64, 0, 0, Wexp + O2 + (size_t)KH * H2, 128, 0,
                                              AC, 128, 100, bl[1], XL, 104);
        cudaEventRecord(eg[10], s2);
        cudaStreamWaitEvent(0, eg[10], 0);
    }

    // ---- layer 3: stride-104 props, overlapped hop-paired ----
    {
        const size_t SL = (size_t)RPAD * 128;
        dim3 g(GM, 2);
        k_expand<<<(NN * 128 + 255) / 256, 256>>>(XL, 104, 128, 104, Ahi, Alo);
        k_prop4p<<<WG, 256>>>(XL, A0, Ahi + SL, Alo + SL);
        cudaEventRecord(ep[11], 0);
        cudaStreamWaitEvent(s2, ep[11], 0);
        k_gemm_bf<7, 0, 2><<<g, 256, 0, s2>>>(128, 0, SL, Wexp + O3, 256, H3,
                                              AC, 224, 200, 0, 0, 0);
        cudaEventRecord(eg[11], s2);
        for (int j = 1; j <= 9; ++j) {
            size_t base = (j & 1) ? 2 * SL : 0;
            if (j >= 2) cudaStreamWaitEvent(0, eg[11 + j - 2], 0);
            k_prop4p<<<WG, 256>>>(A0, A1, Ahi + base, Alo + base);
            k_prop4p<<<WG, 256>>>(A1, A0, Ahi + base + SL, Alo + base + SL);
            cudaEventRecord(ep[11 + j], 0);
            cudaStreamWaitEvent(s2, ep[11 + j], 0);
            k_gemm_bf<7, 1, 2><<<g, 256, 0, s2>>>(128, base, SL,
                                                  Wexp + O3 + (size_t)(2 * j) * H3, 256, H3,
                                                  AC, 224, 200, 0, 0, 0);
            cudaEventRecord(eg[11 + j], s2);
        }
        cudaStreamWaitEvent(0, eg[11 + 8], 0);
        k_prop4p<<<WG, 256>>>(A0, A1, Ahi, Alo);
        cudaEventRecord(ep[21], 0);
        cudaStreamWaitEvent(s2, ep[21], 0);
        k_gemm_bf<7, 2, 1><<<g, 256, 0, s2>>>(128, 0, 0, Wexp + O3 + (size_t)KH * H3, 256, 0,
                                              AC, 224, 200, bl[2], XL, 224);
        cudaEventRecord(eg[21], s2);
        cudaStreamWaitEvent(0, eg[21], 0);
    }

    // ---- layer 4: pipelined Horner, stride-80 t/Y buffers ----
    {
        dim3 g(GM, 1);
        float* Yb[2] = {XL, XL + (size_t)RPAD * 80};
        k_expand<<<(NN * 224 + 255) / 256, 256>>>(XL, 224, 224, 224, Ahi, Alo);
        cudaEventRecord(ep[44], 0);
        cudaStreamWaitEvent(s2, ep[44], 0);
        k_gemm_bf<5, 0, 1><<<g, 256, 0, s2>>>(224, 0, 0, Wexp + O4 + (size_t)KH * H4, 448, 0,
                                              A0, 80, 80, 0, 0, 0);
        cudaEventRecord(eg[43], s2);
        k_gemm_bf<5, 0, 1><<<g, 256, 0, s2>>>(224, 0, 0, Wexp + O4 + (size_t)(KH - 1) * H4,
                                              448, 0, Yb[(KH - 1) & 1], 80, 80, 0, 0, 0);
        cudaEventRecord(eg[22 + KH - 1], s2);
        k_gemm_bf<5, 0, 1><<<g, 256, 0, s2>>>(224, 0, 0, Wexp + O4 + (size_t)(KH - 2) * H4,
                                              448, 0, Yb[(KH - 2) & 1], 80, 80, 0, 0, 0);
        cudaEventRecord(eg[22 + KH - 2], s2);
        cudaStreamWaitEvent(0, eg[43], 0);

        float* t = A0;
        float* o = A1;
        for (int k = KH - 1; k >= 1; --k) {
            cudaStreamWaitEvent(0, eg[22 + k], 0);
            k_prop3add<0><<<WG, 256>>>(t, o, Yb[k & 1], 0);
            cudaEventRecord(ep[22 + k], 0);
            if (k - 2 >= 0) {
                cudaStreamWaitEvent(s2, ep[22 + k], 0);
                k_gemm_bf<5, 0, 1><<<g, 256, 0, s2>>>(224, 0, 0,
                                                      Wexp + O4 + (size_t)(k - 2) * H4,
                                                      448, 0, Yb[(k - 2) & 1], 80, 80, 0, 0, 0);
                cudaEventRecord(eg[22 + k - 2], s2);
            }
            float* tmp = t; t = o; o = tmp;
        }
        cudaStreamWaitEvent(0, eg[22], 0);
        k_prop3add<1><<<WG, 256>>>(t, AC, Yb[0], bl[3]);
    }

    // ---- layer 5: Y-stack in XL, scalar Horner, fused sigmoid ----
    k_y5<<<WG, 256>>>(AC, Wl[4], XL);
    {
        const float* hold = XL + (size_t)KH * RPAD;
        float* cur = A0;
        float* nxt = A1;
        for (int k = KH - 1; k >= 1; --k) {
            k_sprop<1><<<WG, 256>>>(hold, cur, XL + (size_t)k * RPAD, 0);
            hold = cur;
            float* tmp = cur; cur = nxt; nxt = tmp;
        }
        k_sprop<2><<<WG, 256>>>(hold, out, XL, bl[4]);
    }
}